// round 13
// baseline (speedup 1.0000x reference)
#include <cuda_runtime.h>
#include <math.h>

#define VOCAB  8000
#define MAXDEC 50
#define NSTEPS 49
#define SENTINEL 7777

// ---------------- scratch layout (floats) ----------------
#define OFF_PATCH    0ull            // 8192*1280
#define OFF_C1       10485760ull     // 8192*512
#define OFF_C2       14680064ull     // 4096*512
#define OFF_XTBC     16777216ull     // 4096*512
#define OFF_GIF      18874368ull     // 4096*1536
#define OFF_GIB      25165824ull     // 4096*1536
#define OFF_ENCOUT   31457280ull     // 32*128*1024
#define OFF_ENCPROJ  35651584ull     // 32*128*512
#define OFF_HBUF     37748736ull     // 2*2*32*512 (parity, dir, b, j)
#define OFF_COMB     37814272ull     // 32*1024
#define OFF_BRIDGE   37847040ull     // 32*1024
#define OFF_H0BUF    37879808ull     // 2*32*512 (parity ping-pong)
#define OFF_H1BUF    37912576ull     // 2*32*512
#define OFF_CTX      37945344ull     // 32*1024
#define OFF_LOGITS   37978112ull     // 32*8000
#define OFF_TOK      38234112ull     // 32 ints
#define SCRATCH_FLOATS 38234176ull

static __device__ float g_scratch[SCRATCH_FLOATS];

// ---------------- software grid barrier (grid-agnostic, proven to complete) --
__device__ unsigned g_bar_cnt = 0;
__device__ unsigned g_bar_gen = 0;

__device__ __forceinline__ void grid_barrier()
{
    unsigned nblk = gridDim.x;
    __threadfence();                 // release (every thread)
    __syncthreads();
    if (threadIdx.x == 0) {
        unsigned gen = atomicAdd(&g_bar_gen, 0u);
        if (atomicAdd(&g_bar_cnt, 1u) == nblk - 1u) {
            atomicExch(&g_bar_cnt, 0u);
            __threadfence();
            atomicExch(&g_bar_gen, gen + 1u);
        } else {
            while (atomicAdd(&g_bar_gen, 0u) == gen) __nanosleep(64);
        }
    }
    __syncthreads();
    __threadfence();                 // acquire (every thread)
}

// ---------------- standalone GEMM: C[M,N] = act(A[M,K].B[N,K]^T + bias) ------
__global__ void gemm_abt(const float* __restrict__ A, const float* __restrict__ Bm,
                         const float* __restrict__ bias, float* __restrict__ C,
                         int M, int N, int K, int relu)
{
    __shared__ float As[16][65];
    __shared__ float Bs[16][65];
    int tid = threadIdx.x;
    int tx = tid & 15, ty = tid >> 4;
    int m0 = blockIdx.x * 64, n0 = blockIdx.y * 64;
    float acc[4][4];
#pragma unroll
    for (int i = 0; i < 4; i++)
#pragma unroll
        for (int j = 0; j < 4; j++) acc[i][j] = 0.f;

    for (int k0 = 0; k0 < K; k0 += 16) {
#pragma unroll
        for (int r = 0; r < 4; r++) {
            int i  = tid + r * 256;
            int mm = i >> 4, kk = i & 15;
            As[kk][mm] = (m0 + mm < M) ? A[(size_t)(m0 + mm) * K + k0 + kk] : 0.f;
            Bs[kk][mm] = (n0 + mm < N) ? Bm[(size_t)(n0 + mm) * K + k0 + kk] : 0.f;
        }
        __syncthreads();
#pragma unroll
        for (int kk = 0; kk < 16; kk++) {
            float a[4], b[4];
#pragma unroll
            for (int i = 0; i < 4; i++) a[i] = As[kk][ty * 4 + i];
#pragma unroll
            for (int j = 0; j < 4; j++) b[j] = Bs[kk][tx * 4 + j];
#pragma unroll
            for (int i = 0; i < 4; i++)
#pragma unroll
                for (int j = 0; j < 4; j++) acc[i][j] = fmaf(a[i], b[j], acc[i][j]);
        }
        __syncthreads();
    }
#pragma unroll
    for (int i = 0; i < 4; i++) {
        int m = m0 + ty * 4 + i;
        if (m >= M) continue;
#pragma unroll
        for (int j = 0; j < 4; j++) {
            int n = n0 + tx * 4 + j;
            if (n >= N) continue;
            float v = acc[i][j] + (bias ? bias[n] : 0.f);
            if (relu) v = fmaxf(v, 0.f);
            C[(size_t)m * N + n] = v;
        }
    }
}

// ---------------- conv im2col / transpose ----------------
__global__ void im2col1(const float* __restrict__ f, float* __restrict__ patch)
{
    long long idx = (long long)blockIdx.x * 256 + threadIdx.x;
    if (idx >= 8192LL * 1280) return;
    int col = (int)(idx % 1280);
    int row = (int)(idx / 1280);
    int ol = row & 255, b = row >> 8;
    int ic = col / 5, kk = col % 5;
    int l = 2 * ol - 2 + kk;
    patch[idx] = (l >= 0 && l < 512) ? f[((size_t)b * 512 + l) * 256 + ic] : 0.f;
}

__global__ void im2col2(const float* __restrict__ c1, float* __restrict__ patch)
{
    long long idx = (long long)blockIdx.x * 256 + threadIdx.x;
    if (idx >= 4096LL * 2560) return;
    int col = (int)(idx % 2560);
    int row = (int)(idx / 2560);
    int ol = row & 127, b = row >> 7;
    int ic = col / 5, kk = col % 5;
    int l = 2 * ol - 2 + kk;
    patch[idx] = (l >= 0 && l < 256) ? c1[((size_t)b * 256 + l) * 512 + ic] : 0.f;
}

__global__ void xpose_bt(const float* __restrict__ c2, float* __restrict__ xtbc)
{
    int idx = blockIdx.x * 256 + threadIdx.x;
    if (idx >= 4096 * 512) return;
    int c = idx & 511;
    int row = idx >> 9;
    int t = row >> 5, b = row & 31;
    xtbc[idx] = c2[((size_t)b * 128 + t) * 512 + c];
}

// ---------------- persistent encoder: 128 steps, 1 barrier/step --------------
// Job = (dir, 32-col j-tile): 32 jobs/step. Body = validated enc_step_k.
__global__ __launch_bounds__(256) void encoder_loop_k(
    const float* __restrict__ gif, const float* __restrict__ gib,
    const float* __restrict__ WhhF, const float* __restrict__ WhhB,
    const float* __restrict__ bhhF, const float* __restrict__ bhhB,
    float* __restrict__ encout, float* __restrict__ comb, float* __restrict__ hbuf)
{
    __shared__ float As[32][17];
    __shared__ float Bs[3][32][17];
    const int tid = threadIdx.x;
    const int bid = blockIdx.x;
    const int NB  = gridDim.x;

    for (int i = bid * 256 + tid; i < 32768; i += NB * 256) hbuf[i] = 0.f;
    grid_barrier();

    for (int t = 0; t < 128; t++) {
        for (int job = bid; job < 32; job += NB) {
            const int dir = job >> 4;
            const int j0  = (job & 15) * 32;
            const float* Whh = dir ? WhhB : WhhF;
            const float* bhh = dir ? bhhB : bhhF;
            const float* giB = dir ? gib : gif;
            const int tx = tid & 31;
            const int ty = tid >> 5;
            const int j  = j0 + tx;

            const float* hin  = hbuf + (t & 1) * 32768 + dir * 16384;
            float*       hout = hbuf + ((t + 1) & 1) * 32768 + dir * 16384;

            float acc[3][4] = {{0,0,0,0},{0,0,0,0},{0,0,0,0}};

            for (int k0 = 0; k0 < 512; k0 += 16) {
                {
                    int m = tid >> 4, kk = tid & 15;
                    As[m][kk] = hin[m * 512 + k0 + kk];
                    int e = tid + 256; m = e >> 4; kk = e & 15;
                    As[m][kk] = hin[m * 512 + k0 + kk];
                }
#pragma unroll
                for (int i = 0; i < 6; i++) {
                    int e = tid + i * 256;
                    int g = e >> 9, rest = e & 511;
                    int n = rest >> 4, kk = rest & 15;
                    Bs[g][n][kk] = Whh[(size_t)(g * 512 + j0 + n) * 512 + k0 + kk];
                }
                __syncthreads();
#pragma unroll
                for (int kk = 0; kk < 16; kk++) {
                    float b0 = Bs[0][tx][kk], b1 = Bs[1][tx][kk], b2 = Bs[2][tx][kk];
#pragma unroll
                    for (int r = 0; r < 4; r++) {
                        float a = As[ty * 4 + r][kk];
                        acc[0][r] = fmaf(a, b0, acc[0][r]);
                        acc[1][r] = fmaf(a, b1, acc[1][r]);
                        acc[2][r] = fmaf(a, b2, acc[2][r]);
                    }
                }
                __syncthreads();
            }

            const int ts = dir ? (127 - t) : t;
            const float* gi = giB + (size_t)ts * 32 * 1536;
            const float b_r = bhh[j], b_z = bhh[512 + j], b_n = bhh[1024 + j];
#pragma unroll
            for (int r = 0; r < 4; r++) {
                int m = ty * 4 + r;
                float ir = gi[m * 1536 + j], iz = gi[m * 1536 + 512 + j], in = gi[m * 1536 + 1024 + j];
                float rr = 1.f / (1.f + expf(-(ir + acc[0][r] + b_r)));
                float zz = 1.f / (1.f + expf(-(iz + acc[1][r] + b_z)));
                float nn = tanhf(in + rr * (acc[2][r] + b_n));
                float hv = (1.f - zz) * nn + zz * hin[m * 512 + j];
                hout[m * 512 + j] = hv;
                encout[((size_t)m * 128 + ts) * 1024 + dir * 512 + j] = hv;
            }
            __syncthreads();
        }
        grid_barrier();
    }

    // final h at parity 0
    for (int i = bid * 256 + tid; i < 32 * 1024; i += NB * 256) {
        int b = i >> 10, jj = i & 1023;
        comb[i] = (jj < 512) ? hbuf[b * 512 + jj] : hbuf[16384 + b * 512 + (jj - 512)];
    }
}

// ---------------- persistent decoder: 49 steps, 5 barriers/step --------------
// Phase bodies are the validated round-12 kernels, inlined with job loops.
__global__ __launch_bounds__(256) void decoder_loop_k(
    float* __restrict__ S,
    const float* __restrict__ emb, const float* __restrict__ attn_Wd,
    const float* __restrict__ attn_v,
    const float* __restrict__ Wih0, const float* __restrict__ Whh0,
    const float* __restrict__ bih0, const float* __restrict__ bhh0,
    const float* __restrict__ Wih1, const float* __restrict__ Whh1,
    const float* __restrict__ bih1, const float* __restrict__ bhh1,
    const float* __restrict__ projW, const float* __restrict__ projb,
    const float* __restrict__ bridgeW, const float* __restrict__ bridgeb,
    float* __restrict__ out)
{
    __shared__ float As16[16][65];
    __shared__ float Bs16[16][65];
    __shared__ float As32[32][17];
    __shared__ float Bs64[64][17];
    __shared__ float sacc[32][65];
    __shared__ float s_h[512];
    __shared__ float s_dq[512];
    __shared__ float s_sc[128];
    __shared__ float s_red[256];
    __shared__ float sv[256];
    __shared__ int   si[256];

    const int tid = threadIdx.x;
    const int bid = blockIdx.x;
    const int NB  = gridDim.x;
    const int lane = tid & 31, warp = tid >> 5;

    const float* encout  = S + OFF_ENCOUT;
    const float* encproj = S + OFF_ENCPROJ;
    const float* comb    = S + OFF_COMB;
    float* bridge = S + OFF_BRIDGE;
    float* h0buf  = S + OFF_H0BUF;
    float* h1buf  = S + OFF_H1BUF;
    float* ctx    = S + OFF_CTX;
    float* logits = S + OFF_LOGITS;
    int*   tok    = (int*)(S + OFF_TOK);

    // ---- prologue: bridge = comb @ bridgeW^T + b, split, init toks ----
    for (int i = bid * 256 + tid; i < 32 * 1024; i += NB * 256) {
        int b = i >> 10, n = i & 1023;
        const float* a = comb + b * 1024;
        const float* w = bridgeW + (size_t)n * 1024;
        float s = bridgeb[n];
        for (int k = 0; k < 1024; k++) s = fmaf(a[k], w[k], s);
        bridge[i] = s;
    }
    grid_barrier();
    for (int i = bid * 256 + tid; i < 32 * 1024; i += NB * 256) {
        int b = i >> 10, j = i & 1023;
        float v = bridge[i];
        if (j < 512) h0buf[b * 512 + j] = v; else h1buf[b * 512 + (j - 512)] = v;
    }
    if (bid == 0 && tid < 32) { tok[tid] = 1; out[tid * MAXDEC] = 1.0f; }
    grid_barrier();

    for (int s = 0; s < NSTEPS; s++) {
        const int p = s & 1, q = 1 - p;
        const float* h0in = h0buf + p * 16384;
        float*       h0out = h0buf + q * 16384;
        const float* h1in = h1buf + p * 16384;
        float*       h1out = h1buf + q * 16384;

        // ---- phase A: attention (32 jobs) ----
        for (int b = bid; b < 32; b += NB) {
            for (int i = tid; i < 512; i += 256) s_h[i] = h1in[b * 512 + i];
            __syncthreads();
            for (int a = warp; a < 512; a += 8) {
                const float* wr = attn_Wd + (size_t)a * 512;
                float acc = 0.f;
                for (int k = lane; k < 512; k += 32) acc = fmaf(s_h[k], wr[k], acc);
#pragma unroll
                for (int o = 16; o; o >>= 1) acc += __shfl_xor_sync(0xffffffffu, acc, o);
                if (lane == 0) s_dq[a] = acc;
            }
            __syncthreads();
            for (int t = warp; t < 128; t += 8) {
                const float* ep = encproj + ((size_t)b * 128 + t) * 512;
                float acc = 0.f;
                for (int a = lane; a < 512; a += 32)
                    acc = fmaf(tanhf(ep[a] + s_dq[a]), attn_v[a], acc);
#pragma unroll
                for (int o = 16; o; o >>= 1) acc += __shfl_xor_sync(0xffffffffu, acc, o);
                if (lane == 0) s_sc[t] = acc;
            }
            __syncthreads();
            float mv = (tid < 128) ? s_sc[tid] : -INFINITY;
            s_red[tid] = mv; __syncthreads();
            for (int o = 128; o; o >>= 1) {
                if (tid < o) s_red[tid] = fmaxf(s_red[tid], s_red[tid + o]);
                __syncthreads();
            }
            float mx = s_red[0]; __syncthreads();
            float ev = (tid < 128) ? expf(s_sc[tid] - mx) : 0.f;
            s_red[tid] = ev; __syncthreads();
            for (int o = 128; o; o >>= 1) {
                if (tid < o) s_red[tid] += s_red[tid + o];
                __syncthreads();
            }
            float dn = s_red[0]; __syncthreads();
            if (tid < 128) s_sc[tid] = ev / dn;
            __syncthreads();
            for (int j = tid; j < 1024; j += 256) {
                const float* eo = encout + (size_t)b * 131072 + j;
                float acc = 0.f;
#pragma unroll 4
                for (int t = 0; t < 128; t++) acc = fmaf(s_sc[t], eo[(size_t)t * 1024], acc);
                ctx[b * 1024 + j] = acc;
            }
            __syncthreads();
        }
        grid_barrier();

        // ---- phase B: layer-0 gates (32 jobs, j0 = job*16) ----
        for (int job = bid; job < 32; job += NB) {
            const int j0 = job * 16;
            const int tx = tid & 15, ty = tid >> 4;
            const int KX = 1536, KTOT = 2048;
            float acc[2][4] = {{0,0,0,0},{0,0,0,0}};
            for (int k0 = 0; k0 < KTOT; k0 += 16) {
#pragma unroll
                for (int rep = 0; rep < 2; rep++) {
                    int e = tid + rep * 256;
                    int m = e >> 4, kk = e & 15;
                    int k = k0 + kk;
                    float av;
                    if (k < 512) {
                        int tk = tok[m];
                        if (tk < 0) tk = 0;
                        if (tk >= VOCAB) tk = VOCAB - 1;
                        av = emb[(size_t)tk * 512 + k];
                    } else if (k < 1536) av = ctx[m * 1024 + (k - 512)];
                    else av = h0in[m * 512 + (k - 1536)];
                    As32[m][kk] = av;
                }
#pragma unroll
                for (int i = 0; i < 4; i++) {
                    int e = tid + i * 256;
                    int c = e >> 4, kk = e & 15;
                    int k = k0 + kk;
                    int g = c >> 4, jj = c & 15;
                    float bv;
                    if (g < 2) {
                        int row = g * 512 + j0 + jj;
                        bv = (k < KX) ? Wih0[(size_t)row * KX + k] : Whh0[(size_t)row * 512 + (k - KX)];
                    } else if (g == 2) {
                        int row = 1024 + j0 + jj;
                        bv = (k < KX) ? Wih0[(size_t)row * KX + k] : 0.f;
                    } else {
                        int row = 1024 + j0 + jj;
                        bv = (k >= KX) ? Whh0[(size_t)row * 512 + (k - KX)] : 0.f;
                    }
                    Bs64[c][kk] = bv;
                }
                __syncthreads();
#pragma unroll
                for (int kk = 0; kk < 16; kk++) {
                    float a0 = As32[ty * 2][kk], a1 = As32[ty * 2 + 1][kk];
#pragma unroll
                    for (int cc = 0; cc < 4; cc++) {
                        float bv = Bs64[tx * 4 + cc][kk];
                        acc[0][cc] = fmaf(a0, bv, acc[0][cc]);
                        acc[1][cc] = fmaf(a1, bv, acc[1][cc]);
                    }
                }
                __syncthreads();
            }
#pragma unroll
            for (int cc = 0; cc < 4; cc++) {
                sacc[ty * 2][tx * 4 + cc]     = acc[0][cc];
                sacc[ty * 2 + 1][tx * 4 + cc] = acc[1][cc];
            }
            __syncthreads();
            for (int i = tid; i < 512; i += 256) {
                int b = i >> 4, jj = i & 15;
                int j = j0 + jj;
                float r_  = sacc[b][jj]      + bih0[j]        + bhh0[j];
                float z_  = sacc[b][16 + jj] + bih0[512 + j]  + bhh0[512 + j];
                float in_ = sacc[b][32 + jj] + bih0[1024 + j];
                float hn_ = sacc[b][48 + jj] + bhh0[1024 + j];
                float rr = 1.f / (1.f + expf(-r_));
                float zz = 1.f / (1.f + expf(-z_));
                float nn = tanhf(in_ + rr * hn_);
                h0out[b * 512 + j] = (1.f - zz) * nn + zz * h0in[b * 512 + j];
            }
            __syncthreads();
        }
        grid_barrier();

        // ---- phase C: layer-1 gates (32 jobs; A = [h0out | h1in], K=1024) ----
        for (int job = bid; job < 32; job += NB) {
            const int j0 = job * 16;
            const int tx = tid & 15, ty = tid >> 4;
            const int KX = 512, KTOT = 1024;
            float acc[2][4] = {{0,0,0,0},{0,0,0,0}};
            for (int k0 = 0; k0 < KTOT; k0 += 16) {
#pragma unroll
                for (int rep = 0; rep < 2; rep++) {
                    int e = tid + rep * 256;
                    int m = e >> 4, kk = e & 15;
                    int k = k0 + kk;
                    As32[m][kk] = (k < 512) ? h0out[m * 512 + k] : h1in[m * 512 + (k - 512)];
                }
#pragma unroll
                for (int i = 0; i < 4; i++) {
                    int e = tid + i * 256;
                    int c = e >> 4, kk = e & 15;
                    int k = k0 + kk;
                    int g = c >> 4, jj = c & 15;
                    float bv;
                    if (g < 2) {
                        int row = g * 512 + j0 + jj;
                        bv = (k < KX) ? Wih1[(size_t)row * KX + k] : Whh1[(size_t)row * 512 + (k - KX)];
                    } else if (g == 2) {
                        int row = 1024 + j0 + jj;
                        bv = (k < KX) ? Wih1[(size_t)row * KX + k] : 0.f;
                    } else {
                        int row = 1024 + j0 + jj;
                        bv = (k >= KX) ? Whh1[(size_t)row * 512 + (k - KX)] : 0.f;
                    }
                    Bs64[c][kk] = bv;
                }
                __syncthreads();
#pragma unroll
                for (int kk = 0; kk < 16; kk++) {
                    float a0 = As32[ty * 2][kk], a1 = As32[ty * 2 + 1][kk];
#pragma unroll
                    for (int cc = 0; cc < 4; cc++) {
                        float bv = Bs64[tx * 4 + cc][kk];
                        acc[0][cc] = fmaf(a0, bv, acc[0][cc]);
                        acc[1][cc] = fmaf(a1, bv, acc[1][cc]);
                    }
                }
                __syncthreads();
            }
#pragma unroll
            for (int cc = 0; cc < 4; cc++) {
                sacc[ty * 2][tx * 4 + cc]     = acc[0][cc];
                sacc[ty * 2 + 1][tx * 4 + cc] = acc[1][cc];
            }
            __syncthreads();
            for (int i = tid; i < 512; i += 256) {
                int b = i >> 4, jj = i & 15;
                int j = j0 + jj;
                float r_  = sacc[b][jj]      + bih1[j]        + bhh1[j];
                float z_  = sacc[b][16 + jj] + bih1[512 + j]  + bhh1[512 + j];
                float in_ = sacc[b][32 + jj] + bih1[1024 + j];
                float hn_ = sacc[b][48 + jj] + bhh1[1024 + j];
                float rr = 1.f / (1.f + expf(-r_));
                float zz = 1.f / (1.f + expf(-z_));
                float nn = tanhf(in_ + rr * hn_);
                h1out[b * 512 + j] = (1.f - zz) * nn + zz * h1in[b * 512 + j];
            }
            __syncthreads();
        }
        grid_barrier();

        // ---- phase D: logits GEMM (125 jobs, n0 = job*64, K=1536) ----
        for (int job = bid; job < 125; job += NB) {
            const int n0 = job * 64;
            const int tx = tid & 15, ty = tid >> 4;
            const int K = 1536;
            float acc[4][4];
#pragma unroll
            for (int i = 0; i < 4; i++)
#pragma unroll
                for (int j = 0; j < 4; j++) acc[i][j] = 0.f;
            for (int k0 = 0; k0 < K; k0 += 16) {
#pragma unroll
                for (int r = 0; r < 4; r++) {
                    int i  = tid + r * 256;
                    int mm = i >> 4, kk = i & 15;
                    int k = k0 + kk;
                    float av = 0.f;
                    if (mm < 32)
                        av = (k < 512) ? h1out[mm * 512 + k] : ctx[mm * 1024 + (k - 512)];
                    As16[kk][mm] = av;
                    Bs16[kk][mm] = projW[(size_t)(n0 + mm) * K + k];
                }
                __syncthreads();
#pragma unroll
                for (int kk = 0; kk < 16; kk++) {
                    float a[4], b[4];
#pragma unroll
                    for (int i = 0; i < 4; i++) a[i] = As16[kk][ty * 4 + i];
#pragma unroll
                    for (int j = 0; j < 4; j++) b[j] = Bs16[kk][tx * 4 + j];
#pragma unroll
                    for (int i = 0; i < 4; i++)
#pragma unroll
                        for (int j = 0; j < 4; j++) acc[i][j] = fmaf(a[i], b[j], acc[i][j]);
                }
                __syncthreads();
            }
#pragma unroll
            for (int i = 0; i < 4; i++) {
                int m = ty * 4 + i;
                if (m >= 32) continue;
#pragma unroll
                for (int j = 0; j < 4; j++) {
                    int n = n0 + tx * 4 + j;
                    logits[(size_t)m * VOCAB + n] = acc[i][j] + projb[n];
                }
            }
            __syncthreads();
        }
        grid_barrier();

        // ---- phase E: argmax (32 jobs) ----
        for (int b = bid; b < 32; b += NB) {
            float best = -INFINITY; int bi = SENTINEL;
            for (int i = tid; i < VOCAB; i += 256) {
                float v = logits[(size_t)b * VOCAB + i];
                if (v > best) { best = v; bi = i; }
            }
            sv[tid] = best; si[tid] = bi; __syncthreads();
            for (int o = 128; o; o >>= 1) {
                if (tid < o) {
                    if (sv[tid + o] > sv[tid] ||
                        (sv[tid + o] == sv[tid] && si[tid + o] < si[tid])) {
                        sv[tid] = sv[tid + o]; si[tid] = si[tid + o];
                    }
                }
                __syncthreads();
            }
            if (tid == 0) { tok[b] = si[0]; out[b * MAXDEC + s + 1] = (float)si[0]; }
            __syncthreads();
        }
        grid_barrier();
    }
}

// ---------------- host ----------------
static inline unsigned cdiv(unsigned a, unsigned b) { return (a + b - 1) / b; }

static void gemm(const float* A, const float* Bm, const float* bias, float* C,
                 int M, int N, int K, int relu)
{
    dim3 grid(cdiv(M, 64), cdiv(N, 64));
    gemm_abt<<<grid, 256>>>(A, Bm, bias, C, M, N, K, relu);
}

enum {
    I_FEAT, I_CW1, I_CB1, I_CW2, I_CB2,
    I_EWIHF, I_EWHHF, I_EBIHF, I_EBHHF,
    I_EWIHB, I_EWHHB, I_EBIHB, I_EBHHB,
    I_BRW, I_BRB, I_EMB, I_AWE, I_AWD, I_AV,
    I_DWIH0, I_DWHH0, I_DBIH0, I_DBHH0,
    I_DWIH1, I_DWHH1, I_DBIH1, I_DBHH1,
    I_PW, I_PB, N_LOGICAL
};

extern "C" void kernel_launch(void* const* d_in, const int* in_sizes, int n_in,
                              void* d_out, int out_size)
{
    (void)out_size;
    static const int posA[N_LOGICAL] = {
        0, 1, 2, 3, 4,  5, 6, 7, 8,  9, 10, 11, 12,
        13, 14, 15, 16, 17, 18,  19, 20, 21, 22,  23, 24, 25, 26,  27, 28 };
    static const int posB[N_LOGICAL] = {
        26, 7, 5, 8, 6,  21, 19, 25, 23,  20, 18, 24, 22,
        3, 4, 17, 1, 0, 2,  11, 9, 15, 13,  12, 10, 16, 14,  27, 28 };
    static const long long esz[N_LOGICAL] = {
        4194304, 655360, 512, 1310720, 512,
        786432, 786432, 1536, 1536,  786432, 786432, 1536, 1536,
        1048576, 1024, 4096000, 524288, 262144, 512,
        2359296, 786432, 1536, 1536,  786432, 786432, 1536, 1536,
        12288000, 8000 };

    const int* pos = posA;
    if (n_in >= N_LOGICAL && in_sizes) {
        int misB = 0;
        for (int i = 0; i < N_LOGICAL; i++)
            if ((long long)in_sizes[posB[i]] != esz[i]) misB++;
        if (misB == 0) {
            int misA = 0;
            for (int i = 0; i < N_LOGICAL; i++)
                if ((long long)in_sizes[posA[i]] != esz[i]) misA++;
            if (misA > 0) pos = posB;
        }
    }

    const float* features = (const float*)d_in[pos[I_FEAT]];
    const float* conv_w1  = (const float*)d_in[pos[I_CW1]];
    const float* conv_b1  = (const float*)d_in[pos[I_CB1]];
    const float* conv_w2  = (const float*)d_in[pos[I_CW2]];
    const float* conv_b2  = (const float*)d_in[pos[I_CB2]];
    const float* Wih_f    = (const float*)d_in[pos[I_EWIHF]];
    const float* Whh_f    = (const float*)d_in[pos[I_EWHHF]];
    const float* bih_f    = (const float*)d_in[pos[I_EBIHF]];
    const float* bhh_f    = (const float*)d_in[pos[I_EBHHF]];
    const float* Wih_b    = (const float*)d_in[pos[I_EWIHB]];
    const float* Whh_b    = (const float*)d_in[pos[I_EWHHB]];
    const float* bih_b    = (const float*)d_in[pos[I_EBIHB]];
    const float* bhh_b    = (const float*)d_in[pos[I_EBHHB]];
    const float* bridge_W = (const float*)d_in[pos[I_BRW]];
    const float* bridge_b = (const float*)d_in[pos[I_BRB]];
    const float* emb      = (const float*)d_in[pos[I_EMB]];
    const float* attn_We  = (const float*)d_in[pos[I_AWE]];
    const float* attn_Wd  = (const float*)d_in[pos[I_AWD]];
    const float* attn_v   = (const float*)d_in[pos[I_AV]];
    const float* dWih0    = (const float*)d_in[pos[I_DWIH0]];
    const float* dWhh0    = (const float*)d_in[pos[I_DWHH0]];
    const float* dbih0    = (const float*)d_in[pos[I_DBIH0]];
    const float* dbhh0    = (const float*)d_in[pos[I_DBHH0]];
    const float* dWih1    = (const float*)d_in[pos[I_DWIH1]];
    const float* dWhh1    = (const float*)d_in[pos[I_DWHH1]];
    const float* dbih1    = (const float*)d_in[pos[I_DBIH1]];
    const float* dbhh1    = (const float*)d_in[pos[I_DBHH1]];
    const float* proj_W   = (const float*)d_in[pos[I_PW]];
    const float* proj_b   = (const float*)d_in[pos[I_PB]];
    float* out = (float*)d_out;    // __output__ dtype: float32

    float* S = nullptr;
    cudaGetSymbolAddress((void**)&S, g_scratch);

    float* patch   = S + OFF_PATCH;
    float* c1      = S + OFF_C1;
    float* c2      = S + OFF_C2;
    float* xtbc    = S + OFF_XTBC;
    float* gif     = S + OFF_GIF;
    float* gib     = S + OFF_GIB;
    float* encout  = S + OFF_ENCOUT;
    float* encproj = S + OFF_ENCPROJ;
    float* hbuf    = S + OFF_HBUF;
    float* comb    = S + OFF_COMB;

    // ---- co-residency grid sizing for persistent kernels ----
    int dev = 0; cudaGetDevice(&dev);
    int nsm = 0; cudaDeviceGetAttribute(&nsm, cudaDevAttrMultiProcessorCount, dev);
    if (nsm <= 0) nsm = 1;
    int occE = 0, occD = 0;
    cudaOccupancyMaxActiveBlocksPerMultiprocessor(&occE, encoder_loop_k, 256, 0);
    cudaOccupancyMaxActiveBlocksPerMultiprocessor(&occD, decoder_loop_k, 256, 0);
    if (occE < 1) occE = 1;
    if (occD < 1) occD = 1;
    long long ecap = (long long)nsm * occE;
    long long dcap = (long long)nsm * occD;
    int enc_blk = (int)(ecap < 32  ? ecap : 32);
    int dec_blk = (int)(dcap < 125 ? dcap : 125);

    // conv stack (5 nodes)
    im2col1<<<cdiv(8192u * 1280u, 256u), 256>>>(features, patch);
    gemm(patch, conv_w1, conv_b1, c1, 8192, 512, 1280, 1);
    im2col2<<<cdiv(4096u * 2560u, 256u), 256>>>(c1, patch);
    gemm(patch, conv_w2, conv_b2, c2, 4096, 512, 2560, 1);
    xpose_bt<<<cdiv(4096u * 512u, 256u), 256>>>(c2, xtbc);

    // encoder input GEMMs (2 nodes)
    gemm(xtbc, Wih_f, bih_f, gif, 4096, 1536, 512, 0);
    gemm(xtbc, Wih_b, bih_b, gib, 4096, 1536, 512, 0);

    // persistent encoder (1 node)
    encoder_loop_k<<<enc_blk, 256>>>(gif, gib, Whh_f, Whh_b, bhh_f, bhh_b,
                                     encout, comb, hbuf);

    // encproj (1 node)
    gemm(encout, attn_We, nullptr, encproj, 4096, 512, 1024, 0);

    // persistent decoder (1 node)
    decoder_loop_k<<<dec_blk, 256>>>(S, emb, attn_Wd, attn_v,
                                     dWih0, dWhh0, dbih0, dbhh0,
                                     dWih1, dWhh1, dbih1, dbhh1,
                                     proj_W, proj_b, bridge_W, bridge_b, out);
}

// round 14
// speedup vs baseline: 1.7531x; 1.7531x over previous
#include <cuda_runtime.h>
#include <math.h>

#define VOCAB  8000
#define MAXDEC 50
#define NSTEPS 49
#define SENTINEL 7777

// ---------------- scratch layout (floats) ----------------
#define OFF_PATCH    0ull            // 8192*1280
#define OFF_C1       10485760ull     // 8192*512
#define OFF_C2       14680064ull     // 4096*512
#define OFF_XTBC     16777216ull     // 4096*512
#define OFF_GIF      18874368ull     // 4096*1536
#define OFF_GIB      25165824ull     // 4096*1536
#define OFF_ENCOUT   31457280ull     // 32*128*1024
#define OFF_ENCPROJ  35651584ull     // 32*128*512
#define OFF_HBUF     37748736ull     // 2*2*32*512
#define OFF_COMB     37814272ull     // 32*1024
#define OFF_BRIDGE   37847040ull     // 32*1024
#define OFF_H0BUF    37879808ull     // 2*32*512
#define OFF_H1BUF    37912576ull     // 2*32*512
#define OFF_CTX      37945344ull     // 32*1024
#define OFF_LOGITS   37978112ull     // 32*8000
#define OFF_GBUF     38234112ull     // 32*2048 gates0 partial
#define OFF_TOK      38299648ull     // 32 ints
#define SCRATCH_FLOATS 38299712ull

static __device__ float g_scratch[SCRATCH_FLOATS];

// ---------------- software grid barrier ----------------
__device__ unsigned g_bar_cnt = 0;
__device__ unsigned g_bar_gen = 0;

__device__ __forceinline__ void grid_barrier()
{
    unsigned nblk = gridDim.x;
    __threadfence();
    __syncthreads();
    if (threadIdx.x == 0) {
        unsigned gen = atomicAdd(&g_bar_gen, 0u);
        if (atomicAdd(&g_bar_cnt, 1u) == nblk - 1u) {
            atomicExch(&g_bar_cnt, 0u);
            __threadfence();
            atomicExch(&g_bar_gen, gen + 1u);
        } else {
            while (atomicAdd(&g_bar_gen, 0u) == gen) __nanosleep(64);
        }
    }
    __syncthreads();
    __threadfence();
}

// ---------------- standalone GEMM (strided conflict-free tile) ---------------
__global__ void gemm_abt(const float* __restrict__ A, const float* __restrict__ Bm,
                         const float* __restrict__ bias, float* __restrict__ C,
                         int M, int N, int K, int relu)
{
    __shared__ float As[16][65];
    __shared__ float Bs[16][65];
    int tid = threadIdx.x;
    int tx = tid & 15, ty = tid >> 4;
    int m0 = blockIdx.x * 64, n0 = blockIdx.y * 64;
    float acc[4][4];
#pragma unroll
    for (int i = 0; i < 4; i++)
#pragma unroll
        for (int j = 0; j < 4; j++) acc[i][j] = 0.f;

    for (int k0 = 0; k0 < K; k0 += 16) {
#pragma unroll
        for (int r = 0; r < 4; r++) {
            int i  = tid + r * 256;
            int mm = i >> 4, kk = i & 15;
            As[kk][mm] = (m0 + mm < M) ? A[(size_t)(m0 + mm) * K + k0 + kk] : 0.f;
            Bs[kk][mm] = (n0 + mm < N) ? Bm[(size_t)(n0 + mm) * K + k0 + kk] : 0.f;
        }
        __syncthreads();
#pragma unroll
        for (int kk = 0; kk < 16; kk++) {
            float a[4], b[4];
#pragma unroll
            for (int i = 0; i < 4; i++) a[i] = As[kk][ty + 16 * i];
#pragma unroll
            for (int j = 0; j < 4; j++) b[j] = Bs[kk][tx + 16 * j];
#pragma unroll
            for (int i = 0; i < 4; i++)
#pragma unroll
                for (int j = 0; j < 4; j++) acc[i][j] = fmaf(a[i], b[j], acc[i][j]);
        }
        __syncthreads();
    }
#pragma unroll
    for (int i = 0; i < 4; i++) {
        int m = m0 + ty + 16 * i;
        if (m >= M) continue;
#pragma unroll
        for (int j = 0; j < 4; j++) {
            int n = n0 + tx + 16 * j;
            if (n >= N) continue;
            float v = acc[i][j] + (bias ? bias[n] : 0.f);
            if (relu) v = fmaxf(v, 0.f);
            C[(size_t)m * N + n] = v;
        }
    }
}

// ---------------- conv im2col / transpose ----------------
__global__ void im2col1(const float* __restrict__ f, float* __restrict__ patch)
{
    long long idx = (long long)blockIdx.x * 256 + threadIdx.x;
    if (idx >= 8192LL * 1280) return;
    int col = (int)(idx % 1280);
    int row = (int)(idx / 1280);
    int ol = row & 255, b = row >> 8;
    int ic = col / 5, kk = col % 5;
    int l = 2 * ol - 2 + kk;
    patch[idx] = (l >= 0 && l < 512) ? f[((size_t)b * 512 + l) * 256 + ic] : 0.f;
}

__global__ void im2col2(const float* __restrict__ c1, float* __restrict__ patch)
{
    long long idx = (long long)blockIdx.x * 256 + threadIdx.x;
    if (idx >= 4096LL * 2560) return;
    int col = (int)(idx % 2560);
    int row = (int)(idx / 2560);
    int ol = row & 127, b = row >> 7;
    int ic = col / 5, kk = col % 5;
    int l = 2 * ol - 2 + kk;
    patch[idx] = (l >= 0 && l < 256) ? c1[((size_t)b * 256 + l) * 512 + ic] : 0.f;
}

__global__ void xpose_bt(const float* __restrict__ c2, float* __restrict__ xtbc)
{
    int idx = blockIdx.x * 256 + threadIdx.x;
    if (idx >= 4096 * 512) return;
    int c = idx & 511;
    int row = idx >> 9;
    int t = row >> 5, b = row & 31;
    xtbc[idx] = c2[((size_t)b * 128 + t) * 512 + c];
}

// ---------------- persistent encoder (validated round-13 body) ---------------
__global__ __launch_bounds__(256) void encoder_loop_k(
    const float* __restrict__ gif, const float* __restrict__ gib,
    const float* __restrict__ WhhF, const float* __restrict__ WhhB,
    const float* __restrict__ bhhF, const float* __restrict__ bhhB,
    float* __restrict__ encout, float* __restrict__ comb, float* __restrict__ hbuf)
{
    __shared__ float As[32][17];
    __shared__ float Bs[3][32][17];
    const int tid = threadIdx.x;
    const int bid = blockIdx.x;
    const int NB  = gridDim.x;

    for (int i = bid * 256 + tid; i < 32768; i += NB * 256) hbuf[i] = 0.f;
    grid_barrier();

    for (int t = 0; t < 128; t++) {
        for (int job = bid; job < 32; job += NB) {
            const int dir = job >> 4;
            const int j0  = (job & 15) * 32;
            const float* Whh = dir ? WhhB : WhhF;
            const float* bhh = dir ? bhhB : bhhF;
            const float* giB = dir ? gib : gif;
            const int tx = tid & 31;
            const int ty = tid >> 5;
            const int j  = j0 + tx;

            const float* hin  = hbuf + (t & 1) * 32768 + dir * 16384;
            float*       hout = hbuf + ((t + 1) & 1) * 32768 + dir * 16384;

            float acc[3][4] = {{0,0,0,0},{0,0,0,0},{0,0,0,0}};

            for (int k0 = 0; k0 < 512; k0 += 16) {
                {
                    int m = tid >> 4, kk = tid & 15;
                    As[m][kk] = hin[m * 512 + k0 + kk];
                    int e = tid + 256; m = e >> 4; kk = e & 15;
                    As[m][kk] = hin[m * 512 + k0 + kk];
                }
#pragma unroll
                for (int i = 0; i < 6; i++) {
                    int e = tid + i * 256;
                    int g = e >> 9, rest = e & 511;
                    int n = rest >> 4, kk = rest & 15;
                    Bs[g][n][kk] = Whh[(size_t)(g * 512 + j0 + n) * 512 + k0 + kk];
                }
                __syncthreads();
#pragma unroll
                for (int kk = 0; kk < 16; kk++) {
                    float b0 = Bs[0][tx][kk], b1 = Bs[1][tx][kk], b2 = Bs[2][tx][kk];
#pragma unroll
                    for (int r = 0; r < 4; r++) {
                        float a = As[ty * 4 + r][kk];
                        acc[0][r] = fmaf(a, b0, acc[0][r]);
                        acc[1][r] = fmaf(a, b1, acc[1][r]);
                        acc[2][r] = fmaf(a, b2, acc[2][r]);
                    }
                }
                __syncthreads();
            }

            const int ts = dir ? (127 - t) : t;
            const float* gi = giB + (size_t)ts * 32 * 1536;
            const float b_r = bhh[j], b_z = bhh[512 + j], b_n = bhh[1024 + j];
#pragma unroll
            for (int r = 0; r < 4; r++) {
                int m = ty * 4 + r;
                float ir = gi[m * 1536 + j], iz = gi[m * 1536 + 512 + j], in = gi[m * 1536 + 1024 + j];
                float rr = 1.f / (1.f + expf(-(ir + acc[0][r] + b_r)));
                float zz = 1.f / (1.f + expf(-(iz + acc[1][r] + b_z)));
                float nn = tanhf(in + rr * (acc[2][r] + b_n));
                float hv = (1.f - zz) * nn + zz * hin[m * 512 + j];
                hout[m * 512 + j] = hv;
                encout[((size_t)m * 128 + ts) * 1024 + dir * 512 + j] = hv;
            }
            __syncthreads();
        }
        grid_barrier();
    }

    for (int i = bid * 256 + tid; i < 32 * 1024; i += NB * 256) {
        int b = i >> 10, jj = i & 1023;
        comb[i] = (jj < 512) ? hbuf[b * 512 + jj] : hbuf[16384 + b * 512 + (jj - 512)];
    }
}

// ---------------- persistent decoder with overlapped windows -----------------
__global__ __launch_bounds__(256) void decoder_loop_k(
    float* __restrict__ S,
    const float* __restrict__ emb, const float* __restrict__ attn_Wd,
    const float* __restrict__ attn_v,
    const float* __restrict__ Wih0, const float* __restrict__ Whh0,
    const float* __restrict__ bih0, const float* __restrict__ bhh0,
    const float* __restrict__ Wih1, const float* __restrict__ Whh1,
    const float* __restrict__ bih1, const float* __restrict__ bhh1,
    const float* __restrict__ projW, const float* __restrict__ projb,
    const float* __restrict__ bridgeW, const float* __restrict__ bridgeb,
    float* __restrict__ out)
{
    __shared__ float As16[16][65];
    __shared__ float Bs16[16][65];
    __shared__ float As32[32][17];
    __shared__ float Bs64[64][17];
    __shared__ float sacc[32][65];
    __shared__ float s_h[512];
    __shared__ float s_dq[512];
    __shared__ float s_sc[128];
    __shared__ float s_red[256];
    __shared__ float sv[256];
    __shared__ int   si[256];

    const int tid = threadIdx.x;
    const int bid = blockIdx.x;
    const int NB  = gridDim.x;
    const int lane = tid & 31, warp = tid >> 5;
    const int tx = tid & 15, ty = tid >> 4;

    const float* encout  = S + OFF_ENCOUT;
    const float* encproj = S + OFF_ENCPROJ;
    const float* comb    = S + OFF_COMB;
    float* bridge = S + OFF_BRIDGE;
    float* h0buf  = S + OFF_H0BUF;
    float* h1buf  = S + OFF_H1BUF;
    float* ctx    = S + OFF_CTX;
    float* logits = S + OFF_LOGITS;
    float* gbuf   = S + OFF_GBUF;
    int*   tok    = (int*)(S + OFF_TOK);

    // ---- prologue ----
    for (int i = bid * 256 + tid; i < 32 * 1024; i += NB * 256) {
        int b = i >> 10, n = i & 1023;
        const float* a = comb + b * 1024;
        const float* w = bridgeW + (size_t)n * 1024;
        float s = bridgeb[n];
        for (int k = 0; k < 1024; k++) s = fmaf(a[k], w[k], s);
        bridge[i] = s;
    }
    grid_barrier();
    for (int i = bid * 256 + tid; i < 32 * 1024; i += NB * 256) {
        int b = i >> 10, j = i & 1023;
        float v = bridge[i];
        if (j < 512) h0buf[b * 512 + j] = v; else h1buf[b * 512 + (j - 512)] = v;
    }
    if (bid == 0 && tid < 32) { tok[tid] = 1; out[tid * MAXDEC] = 1.0f; }
    grid_barrier();

    for (int s = 0; s < NSTEPS; s++) {
        const int p = s & 1, q = 1 - p;
        const float* h0in = h0buf + p * 16384;
        float*       h0out = h0buf + q * 16384;
        const float* h1in = h1buf + p * 16384;
        float*       h1out = h1buf + q * 16384;

        // ==== W1: attention (jobs 0..31) || gates0 partial over emb+h0 K (jobs 32..63)
        for (int job = bid; job < 64; job += NB) {
            if (job < 32) {
                int b = job;
                for (int i = tid; i < 512; i += 256) s_h[i] = h1in[b * 512 + i];
                __syncthreads();
                for (int a = warp; a < 512; a += 8) {
                    const float* wr = attn_Wd + (size_t)a * 512;
                    float acc = 0.f;
                    for (int k = lane; k < 512; k += 32) acc = fmaf(s_h[k], wr[k], acc);
#pragma unroll
                    for (int o = 16; o; o >>= 1) acc += __shfl_xor_sync(0xffffffffu, acc, o);
                    if (lane == 0) s_dq[a] = acc;
                }
                __syncthreads();
                for (int t = warp; t < 128; t += 8) {
                    const float* ep = encproj + ((size_t)b * 128 + t) * 512;
                    float acc = 0.f;
                    for (int a = lane; a < 512; a += 32)
                        acc = fmaf(tanhf(ep[a] + s_dq[a]), attn_v[a], acc);
#pragma unroll
                    for (int o = 16; o; o >>= 1) acc += __shfl_xor_sync(0xffffffffu, acc, o);
                    if (lane == 0) s_sc[t] = acc;
                }
                __syncthreads();
                float mv = (tid < 128) ? s_sc[tid] : -INFINITY;
                s_red[tid] = mv; __syncthreads();
                for (int o = 128; o; o >>= 1) {
                    if (tid < o) s_red[tid] = fmaxf(s_red[tid], s_red[tid + o]);
                    __syncthreads();
                }
                float mx = s_red[0]; __syncthreads();
                float ev = (tid < 128) ? expf(s_sc[tid] - mx) : 0.f;
                s_red[tid] = ev; __syncthreads();
                for (int o = 128; o; o >>= 1) {
                    if (tid < o) s_red[tid] += s_red[tid + o];
                    __syncthreads();
                }
                float dn = s_red[0]; __syncthreads();
                if (tid < 128) s_sc[tid] = ev / dn;
                __syncthreads();
                for (int j = tid; j < 1024; j += 256) {
                    const float* eo = encout + (size_t)b * 131072 + j;
                    float acc = 0.f;
#pragma unroll 4
                    for (int t = 0; t < 128; t++) acc = fmaf(s_sc[t], eo[(size_t)t * 1024], acc);
                    ctx[b * 1024 + j] = acc;
                }
                __syncthreads();
            } else {
                // gates0 partial: K over {0..511 (emb), 1536..2047 (h0)}
                const int jobx = job - 32;
                const int j0 = jobx * 16;
                float acc[2][4] = {{0,0,0,0},{0,0,0,0}};
                for (int kb = 0; kb < 1024; kb += 16) {
                    const int k0 = (kb < 512) ? kb : (kb + 1024);
#pragma unroll
                    for (int rep = 0; rep < 2; rep++) {
                        int e = tid + rep * 256;
                        int m = e >> 4, kk = e & 15;
                        int k = k0 + kk;
                        float av;
                        if (k < 512) {
                            int tk = tok[m];
                            if (tk < 0) tk = 0;
                            if (tk >= VOCAB) tk = VOCAB - 1;
                            av = emb[(size_t)tk * 512 + k];
                        } else av = h0in[m * 512 + (k - 1536)];
                        As32[m][kk] = av;
                    }
#pragma unroll
                    for (int i = 0; i < 4; i++) {
                        int e = tid + i * 256;
                        int c = e >> 4, kk = e & 15;
                        int k = k0 + kk;
                        int g = c >> 4, jj = c & 15;
                        float bv;
                        if (g < 2) {
                            int row = g * 512 + j0 + jj;
                            bv = (k < 1536) ? Wih0[(size_t)row * 1536 + k]
                                            : Whh0[(size_t)row * 512 + (k - 1536)];
                        } else if (g == 2) {
                            int row = 1024 + j0 + jj;
                            bv = (k < 1536) ? Wih0[(size_t)row * 1536 + k] : 0.f;
                        } else {
                            int row = 1024 + j0 + jj;
                            bv = (k >= 1536) ? Whh0[(size_t)row * 512 + (k - 1536)] : 0.f;
                        }
                        Bs64[c][kk] = bv;
                    }
                    __syncthreads();
#pragma unroll
                    for (int kk = 0; kk < 16; kk++) {
                        float a0 = As32[ty * 2][kk], a1 = As32[ty * 2 + 1][kk];
#pragma unroll
                        for (int cc = 0; cc < 4; cc++) {
                            float bv = Bs64[tx + 16 * cc][kk];
                            acc[0][cc] = fmaf(a0, bv, acc[0][cc]);
                            acc[1][cc] = fmaf(a1, bv, acc[1][cc]);
                        }
                    }
                    __syncthreads();
                }
#pragma unroll
                for (int rep = 0; rep < 2; rep++)
#pragma unroll
                    for (int cc = 0; cc < 4; cc++)
                        gbuf[(ty * 2 + rep) * 2048 + jobx * 64 + tx + 16 * cc] = acc[rep][cc];
                __syncthreads();
            }
        }
        grid_barrier();

        // ==== W2: gates0 finalize (ctx K, jobs 0..31) || logits-ctx (jobs 32..156)
        for (int job = bid; job < 157; job += NB) {
            if (job < 32) {
                const int j0 = job * 16;
                float acc[2][4];
#pragma unroll
                for (int rep = 0; rep < 2; rep++)
#pragma unroll
                    for (int cc = 0; cc < 4; cc++)
                        acc[rep][cc] = gbuf[(ty * 2 + rep) * 2048 + job * 64 + tx + 16 * cc];
                for (int k0 = 512; k0 < 1536; k0 += 16) {
#pragma unroll
                    for (int rep = 0; rep < 2; rep++) {
                        int e = tid + rep * 256;
                        int m = e >> 4, kk = e & 15;
                        As32[m][kk] = ctx[m * 1024 + (k0 + kk - 512)];
                    }
#pragma unroll
                    for (int i = 0; i < 4; i++) {
                        int e = tid + i * 256;
                        int c = e >> 4, kk = e & 15;
                        int k = k0 + kk;
                        int g = c >> 4, jj = c & 15;
                        float bv;
                        if (g < 2) {
                            int row = g * 512 + j0 + jj;
                            bv = Wih0[(size_t)row * 1536 + k];
                        } else if (g == 2) {
                            int row = 1024 + j0 + jj;
                            bv = Wih0[(size_t)row * 1536 + k];
                        } else bv = 0.f;
                        Bs64[c][kk] = bv;
                    }
                    __syncthreads();
#pragma unroll
                    for (int kk = 0; kk < 16; kk++) {
                        float a0 = As32[ty * 2][kk], a1 = As32[ty * 2 + 1][kk];
#pragma unroll
                        for (int cc = 0; cc < 4; cc++) {
                            float bv = Bs64[tx + 16 * cc][kk];
                            acc[0][cc] = fmaf(a0, bv, acc[0][cc]);
                            acc[1][cc] = fmaf(a1, bv, acc[1][cc]);
                        }
                    }
                    __syncthreads();
                }
#pragma unroll
                for (int rep = 0; rep < 2; rep++)
#pragma unroll
                    for (int cc = 0; cc < 4; cc++)
                        sacc[ty * 2 + rep][tx + 16 * cc] = acc[rep][cc];
                __syncthreads();
                for (int i = tid; i < 512; i += 256) {
                    int b = i >> 4, jj = i & 15;
                    int j = j0 + jj;
                    float r_  = sacc[b][jj]      + bih0[j]        + bhh0[j];
                    float z_  = sacc[b][16 + jj] + bih0[512 + j]  + bhh0[512 + j];
                    float in_ = sacc[b][32 + jj] + bih0[1024 + j];
                    float hn_ = sacc[b][48 + jj] + bhh0[1024 + j];
                    float rr = 1.f / (1.f + expf(-r_));
                    float zz = 1.f / (1.f + expf(-z_));
                    float nn = tanhf(in_ + rr * hn_);
                    h0out[b * 512 + j] = (1.f - zz) * nn + zz * h0in[b * 512 + j];
                }
                __syncthreads();
            } else {
                // logits partial: ctx K (projW cols 512..1535), write with bias
                const int n0 = (job - 32) * 64;
                float acc[2][4] = {{0,0,0,0},{0,0,0,0}};
                for (int k0 = 512; k0 < 1536; k0 += 16) {
#pragma unroll
                    for (int r = 0; r < 4; r++) {
                        int i  = tid + r * 256;
                        int mm = i >> 4, kk = i & 15;
                        int k = k0 + kk;
                        As16[kk][mm] = (mm < 32) ? ctx[mm * 1024 + (k - 512)] : 0.f;
                        Bs16[kk][mm] = projW[(size_t)(n0 + mm) * 1536 + k];
                    }
                    __syncthreads();
#pragma unroll
                    for (int kk = 0; kk < 16; kk++) {
                        float a0 = As16[kk][ty], a1 = As16[kk][ty + 16];
#pragma unroll
                        for (int j = 0; j < 4; j++) {
                            float bv = Bs16[kk][tx + 16 * j];
                            acc[0][j] = fmaf(a0, bv, acc[0][j]);
                            acc[1][j] = fmaf(a1, bv, acc[1][j]);
                        }
                    }
                    __syncthreads();
                }
#pragma unroll
                for (int i = 0; i < 2; i++) {
                    int m = ty + 16 * i;
#pragma unroll
                    for (int j = 0; j < 4; j++) {
                        int n = n0 + tx + 16 * j;
                        logits[(size_t)m * VOCAB + n] = acc[i][j] + projb[n];
                    }
                }
                __syncthreads();
            }
        }
        grid_barrier();

        // ==== W3: gates1 (A = [h0out | h1in], K=1024), 32 jobs
        for (int job = bid; job < 32; job += NB) {
            const int j0 = job * 16;
            float acc[2][4] = {{0,0,0,0},{0,0,0,0}};
            for (int k0 = 0; k0 < 1024; k0 += 16) {
#pragma unroll
                for (int rep = 0; rep < 2; rep++) {
                    int e = tid + rep * 256;
                    int m = e >> 4, kk = e & 15;
                    int k = k0 + kk;
                    As32[m][kk] = (k < 512) ? h0out[m * 512 + k] : h1in[m * 512 + (k - 512)];
                }
#pragma unroll
                for (int i = 0; i < 4; i++) {
                    int e = tid + i * 256;
                    int c = e >> 4, kk = e & 15;
                    int k = k0 + kk;
                    int g = c >> 4, jj = c & 15;
                    float bv;
                    if (g < 2) {
                        int row = g * 512 + j0 + jj;
                        bv = (k < 512) ? Wih1[(size_t)row * 512 + k]
                                       : Whh1[(size_t)row * 512 + (k - 512)];
                    } else if (g == 2) {
                        int row = 1024 + j0 + jj;
                        bv = (k < 512) ? Wih1[(size_t)row * 512 + k] : 0.f;
                    } else {
                        int row = 1024 + j0 + jj;
                        bv = (k >= 512) ? Whh1[(size_t)row * 512 + (k - 512)] : 0.f;
                    }
                    Bs64[c][kk] = bv;
                }
                __syncthreads();
#pragma unroll
                for (int kk = 0; kk < 16; kk++) {
                    float a0 = As32[ty * 2][kk], a1 = As32[ty * 2 + 1][kk];
#pragma unroll
                    for (int cc = 0; cc < 4; cc++) {
                        float bv = Bs64[tx + 16 * cc][kk];
                        acc[0][cc] = fmaf(a0, bv, acc[0][cc]);
                        acc[1][cc] = fmaf(a1, bv, acc[1][cc]);
                    }
                }
                __syncthreads();
            }
#pragma unroll
            for (int rep = 0; rep < 2; rep++)
#pragma unroll
                for (int cc = 0; cc < 4; cc++)
                    sacc[ty * 2 + rep][tx + 16 * cc] = acc[rep][cc];
            __syncthreads();
            for (int i = tid; i < 512; i += 256) {
                int b = i >> 4, jj = i & 15;
                int j = j0 + jj;
                float r_  = sacc[b][jj]      + bih1[j]        + bhh1[j];
                float z_  = sacc[b][16 + jj] + bih1[512 + j]  + bhh1[512 + j];
                float in_ = sacc[b][32 + jj] + bih1[1024 + j];
                float hn_ = sacc[b][48 + jj] + bhh1[1024 + j];
                float rr = 1.f / (1.f + expf(-r_));
                float zz = 1.f / (1.f + expf(-z_));
                float nn = tanhf(in_ + rr * hn_);
                h1out[b * 512 + j] = (1.f - zz) * nn + zz * h1in[b * 512 + j];
            }
            __syncthreads();
        }
        grid_barrier();

        // ==== W4: logits += h1 part (K=512), 125 jobs
        for (int job = bid; job < 125; job += NB) {
            const int n0 = job * 64;
            float acc[2][4] = {{0,0,0,0},{0,0,0,0}};
            for (int k0 = 0; k0 < 512; k0 += 16) {
#pragma unroll
                for (int r = 0; r < 4; r++) {
                    int i  = tid + r * 256;
                    int mm = i >> 4, kk = i & 15;
                    int k = k0 + kk;
                    As16[kk][mm] = (mm < 32) ? h1out[mm * 512 + k] : 0.f;
                    Bs16[kk][mm] = projW[(size_t)(n0 + mm) * 1536 + k];
                }
                __syncthreads();
#pragma unroll
                for (int kk = 0; kk < 16; kk++) {
                    float a0 = As16[kk][ty], a1 = As16[kk][ty + 16];
#pragma unroll
                    for (int j = 0; j < 4; j++) {
                        float bv = Bs16[kk][tx + 16 * j];
                        acc[0][j] = fmaf(a0, bv, acc[0][j]);
                        acc[1][j] = fmaf(a1, bv, acc[1][j]);
                    }
                }
                __syncthreads();
            }
#pragma unroll
            for (int i = 0; i < 2; i++) {
                int m = ty + 16 * i;
#pragma unroll
                for (int j = 0; j < 4; j++) {
                    int n = n0 + tx + 16 * j;
                    logits[(size_t)m * VOCAB + n] += acc[i][j];
                }
            }
            __syncthreads();
        }
        grid_barrier();

        // ==== W5: argmax, 32 jobs
        for (int b = bid; b < 32; b += NB) {
            float best = -INFINITY; int bi = SENTINEL;
            for (int i = tid; i < VOCAB; i += 256) {
                float v = logits[(size_t)b * VOCAB + i];
                if (v > best) { best = v; bi = i; }
            }
            sv[tid] = best; si[tid] = bi; __syncthreads();
            for (int o = 128; o; o >>= 1) {
                if (tid < o) {
                    if (sv[tid + o] > sv[tid] ||
                        (sv[tid + o] == sv[tid] && si[tid + o] < si[tid])) {
                        sv[tid] = sv[tid + o]; si[tid] = si[tid + o];
                    }
                }
                __syncthreads();
            }
            if (tid == 0) { tok[b] = si[0]; out[b * MAXDEC + s + 1] = (float)si[0]; }
            __syncthreads();
        }
        grid_barrier();
    }
}

// ---------------- host ----------------
static inline unsigned cdiv(unsigned a, unsigned b) { return (a + b - 1) / b; }

static void gemm(const float* A, const float* Bm, const float* bias, float* C,
                 int M, int N, int K, int relu)
{
    dim3 grid(cdiv(M, 64), cdiv(N, 64));
    gemm_abt<<<grid, 256>>>(A, Bm, bias, C, M, N, K, relu);
}

enum {
    I_FEAT, I_CW1, I_CB1, I_CW2, I_CB2,
    I_EWIHF, I_EWHHF, I_EBIHF, I_EBHHF,
    I_EWIHB, I_EWHHB, I_EBIHB, I_EBHHB,
    I_BRW, I_BRB, I_EMB, I_AWE, I_AWD, I_AV,
    I_DWIH0, I_DWHH0, I_DBIH0, I_DBHH0,
    I_DWIH1, I_DWHH1, I_DBIH1, I_DBHH1,
    I_PW, I_PB, N_LOGICAL
};

extern "C" void kernel_launch(void* const* d_in, const int* in_sizes, int n_in,
                              void* d_out, int out_size)
{
    (void)out_size;
    static const int posA[N_LOGICAL] = {
        0, 1, 2, 3, 4,  5, 6, 7, 8,  9, 10, 11, 12,
        13, 14, 15, 16, 17, 18,  19, 20, 21, 22,  23, 24, 25, 26,  27, 28 };
    static const int posB[N_LOGICAL] = {
        26, 7, 5, 8, 6,  21, 19, 25, 23,  20, 18, 24, 22,
        3, 4, 17, 1, 0, 2,  11, 9, 15, 13,  12, 10, 16, 14,  27, 28 };
    static const long long esz[N_LOGICAL] = {
        4194304, 655360, 512, 1310720, 512,
        786432, 786432, 1536, 1536,  786432, 786432, 1536, 1536,
        1048576, 1024, 4096000, 524288, 262144, 512,
        2359296, 786432, 1536, 1536,  786432, 786432, 1536, 1536,
        12288000, 8000 };

    const int* pos = posA;
    if (n_in >= N_LOGICAL && in_sizes) {
        int misB = 0;
        for (int i = 0; i < N_LOGICAL; i++)
            if ((long long)in_sizes[posB[i]] != esz[i]) misB++;
        if (misB == 0) {
            int misA = 0;
            for (int i = 0; i < N_LOGICAL; i++)
                if ((long long)in_sizes[posA[i]] != esz[i]) misA++;
            if (misA > 0) pos = posB;
        }
    }

    const float* features = (const float*)d_in[pos[I_FEAT]];
    const float* conv_w1  = (const float*)d_in[pos[I_CW1]];
    const float* conv_b1  = (const float*)d_in[pos[I_CB1]];
    const float* conv_w2  = (const float*)d_in[pos[I_CW2]];
    const float* conv_b2  = (const float*)d_in[pos[I_CB2]];
    const float* Wih_f    = (const float*)d_in[pos[I_EWIHF]];
    const float* Whh_f    = (const float*)d_in[pos[I_EWHHF]];
    const float* bih_f    = (const float*)d_in[pos[I_EBIHF]];
    const float* bhh_f    = (const float*)d_in[pos[I_EBHHF]];
    const float* Wih_b    = (const float*)d_in[pos[I_EWIHB]];
    const float* Whh_b    = (const float*)d_in[pos[I_EWHHB]];
    const float* bih_b    = (const float*)d_in[pos[I_EBIHB]];
    const float* bhh_b    = (const float*)d_in[pos[I_EBHHB]];
    const float* bridge_W = (const float*)d_in[pos[I_BRW]];
    const float* bridge_b = (const float*)d_in[pos[I_BRB]];
    const float* emb      = (const float*)d_in[pos[I_EMB]];
    const float* attn_We  = (const float*)d_in[pos[I_AWE]];
    const float* attn_Wd  = (const float*)d_in[pos[I_AWD]];
    const float* attn_v   = (const float*)d_in[pos[I_AV]];
    const float* dWih0    = (const float*)d_in[pos[I_DWIH0]];
    const float* dWhh0    = (const float*)d_in[pos[I_DWHH0]];
    const float* dbih0    = (const float*)d_in[pos[I_DBIH0]];
    const float* dbhh0    = (const float*)d_in[pos[I_DBHH0]];
    const float* dWih1    = (const float*)d_in[pos[I_DWIH1]];
    const float* dWhh1    = (const float*)d_in[pos[I_DWHH1]];
    const float* dbih1    = (const float*)d_in[pos[I_DBIH1]];
    const float* dbhh1    = (const float*)d_in[pos[I_DBHH1]];
    const float* proj_W   = (const float*)d_in[pos[I_PW]];
    const float* proj_b   = (const float*)d_in[pos[I_PB]];
    float* out = (float*)d_out;

    float* S = nullptr;
    cudaGetSymbolAddress((void**)&S, g_scratch);

    float* patch   = S + OFF_PATCH;
    float* c1      = S + OFF_C1;
    float* c2      = S + OFF_C2;
    float* xtbc    = S + OFF_XTBC;
    float* gif     = S + OFF_GIF;
    float* gib     = S + OFF_GIB;
    float* encout  = S + OFF_ENCOUT;
    float* encproj = S + OFF_ENCPROJ;
    float* hbuf    = S + OFF_HBUF;
    float* comb    = S + OFF_COMB;

    int dev = 0; cudaGetDevice(&dev);
    int nsm = 0; cudaDeviceGetAttribute(&nsm, cudaDevAttrMultiProcessorCount, dev);
    if (nsm <= 0) nsm = 1;
    int occE = 0, occD = 0;
    cudaOccupancyMaxActiveBlocksPerMultiprocessor(&occE, encoder_loop_k, 256, 0);
    cudaOccupancyMaxActiveBlocksPerMultiprocessor(&occD, decoder_loop_k, 256, 0);
    if (occE < 1) occE = 1;
    if (occD < 1) occD = 1;
    long long ecap = (long long)nsm * occE;
    long long dcap = (long long)nsm * occD;
    int enc_blk = (int)(ecap < 32  ? ecap : 32);
    int dec_blk = (int)(dcap < 157 ? dcap : 157);

    im2col1<<<cdiv(8192u * 1280u, 256u), 256>>>(features, patch);
    gemm(patch, conv_w1, conv_b1, c1, 8192, 512, 1280, 1);
    im2col2<<<cdiv(4096u * 2560u, 256u), 256>>>(c1, patch);
    gemm(patch, conv_w2, conv_b2, c2, 4096, 512, 2560, 1);
    xpose_bt<<<cdiv(4096u * 512u, 256u), 256>>>(c2, xtbc);

    gemm(xtbc, Wih_f, bih_f, gif, 4096, 1536, 512, 0);
    gemm(xtbc, Wih_b, bih_b, gib, 4096, 1536, 512, 0);

    encoder_loop_k<<<enc_blk, 256>>>(gif, gib, Whh_f, Whh_b, bhh_f, bhh_b,
                                     encout, comb, hbuf);

    gemm(encout, attn_We, nullptr, encproj, 4096, 512, 1024, 0);

    decoder_loop_k<<<dec_blk, 256>>>(S, emb, attn_Wd, attn_v,
                                     dWih0, dWhh0, dbih0, dbhh0,
                                     dWih1, dWhh1, dbih1, dbhh1,
                                     proj_W, proj_b, bridge_W, bridge_b, out);
}

// round 15
// speedup vs baseline: 1.7932x; 1.0229x over previous
#include <cuda_runtime.h>
#include <math.h>

#define VOCAB  8000
#define MAXDEC 50
#define NSTEPS 49
#define SENTINEL 7777

// ---------------- scratch layout (floats) ----------------
#define OFF_PATCH    0ull            // 8192*1280
#define OFF_C1       10485760ull     // 8192*512
#define OFF_C2       14680064ull     // 4096*512
#define OFF_XTBC     16777216ull     // 4096*512
#define OFF_GIF      18874368ull     // 4096*1536
#define OFF_GIB      25165824ull     // 4096*1536
#define OFF_ENCOUT   31457280ull     // 32*128*1024
#define OFF_ENCPROJ  35651584ull     // 32*128*512
#define OFF_HBUF     37748736ull     // 2*2*32*512
#define OFF_COMB     37814272ull     // 32*1024
#define OFF_BRIDGE   37847040ull     // 32*1024
#define OFF_H0BUF    37879808ull     // 2*32*512
#define OFF_H1BUF    37912576ull     // 2*32*512
#define OFF_CTX      37945344ull     // 32*1024
#define OFF_LOGITS   37978112ull     // 32*8000
#define OFF_GBUF     38234112ull     // 32*2048 gates0 partial
#define OFF_GBUF1    38299648ull     // 32*2048 gates1 h-part partial
#define OFF_TOK      38365184ull     // 32 ints
#define SCRATCH_FLOATS 38365248ull

static __device__ float g_scratch[SCRATCH_FLOATS];

// ---------------- software grid barrier (volatile-poll release) --------------
__device__ unsigned g_bar_cnt = 0;
__device__ unsigned g_bar_gen = 0;

__device__ __forceinline__ void grid_barrier()
{
    unsigned nblk = gridDim.x;
    __threadfence();
    __syncthreads();
    if (threadIdx.x == 0) {
        unsigned gen = *(volatile unsigned*)&g_bar_gen;
        if (atomicAdd(&g_bar_cnt, 1u) == nblk - 1u) {
            atomicExch(&g_bar_cnt, 0u);
            __threadfence();
            *(volatile unsigned*)&g_bar_gen = gen + 1u;
        } else {
            while (*(volatile unsigned*)&g_bar_gen == gen) __nanosleep(32);
        }
    }
    __syncthreads();
    __threadfence();
}

// ---------------- standalone GEMM (strided conflict-free tile) ---------------
__global__ void gemm_abt(const float* __restrict__ A, const float* __restrict__ Bm,
                         const float* __restrict__ bias, float* __restrict__ C,
                         int M, int N, int K, int relu)
{
    __shared__ float As[16][65];
    __shared__ float Bs[16][65];
    int tid = threadIdx.x;
    int tx = tid & 15, ty = tid >> 4;
    int m0 = blockIdx.x * 64, n0 = blockIdx.y * 64;
    float acc[4][4];
#pragma unroll
    for (int i = 0; i < 4; i++)
#pragma unroll
        for (int j = 0; j < 4; j++) acc[i][j] = 0.f;

    for (int k0 = 0; k0 < K; k0 += 16) {
#pragma unroll
        for (int r = 0; r < 4; r++) {
            int i  = tid + r * 256;
            int mm = i >> 4, kk = i & 15;
            As[kk][mm] = (m0 + mm < M) ? A[(size_t)(m0 + mm) * K + k0 + kk] : 0.f;
            Bs[kk][mm] = (n0 + mm < N) ? Bm[(size_t)(n0 + mm) * K + k0 + kk] : 0.f;
        }
        __syncthreads();
#pragma unroll
        for (int kk = 0; kk < 16; kk++) {
            float a[4], b[4];
#pragma unroll
            for (int i = 0; i < 4; i++) a[i] = As[kk][ty + 16 * i];
#pragma unroll
            for (int j = 0; j < 4; j++) b[j] = Bs[kk][tx + 16 * j];
#pragma unroll
            for (int i = 0; i < 4; i++)
#pragma unroll
                for (int j = 0; j < 4; j++) acc[i][j] = fmaf(a[i], b[j], acc[i][j]);
        }
        __syncthreads();
    }
#pragma unroll
    for (int i = 0; i < 4; i++) {
        int m = m0 + ty + 16 * i;
        if (m >= M) continue;
#pragma unroll
        for (int j = 0; j < 4; j++) {
            int n = n0 + tx + 16 * j;
            if (n >= N) continue;
            float v = acc[i][j] + (bias ? bias[n] : 0.f);
            if (relu) v = fmaxf(v, 0.f);
            C[(size_t)m * N + n] = v;
        }
    }
}

// ---------------- conv im2col / transpose ----------------
__global__ void im2col1(const float* __restrict__ f, float* __restrict__ patch)
{
    long long idx = (long long)blockIdx.x * 256 + threadIdx.x;
    if (idx >= 8192LL * 1280) return;
    int col = (int)(idx % 1280);
    int row = (int)(idx / 1280);
    int ol = row & 255, b = row >> 8;
    int ic = col / 5, kk = col % 5;
    int l = 2 * ol - 2 + kk;
    patch[idx] = (l >= 0 && l < 512) ? f[((size_t)b * 512 + l) * 256 + ic] : 0.f;
}

__global__ void im2col2(const float* __restrict__ c1, float* __restrict__ patch)
{
    long long idx = (long long)blockIdx.x * 256 + threadIdx.x;
    if (idx >= 4096LL * 2560) return;
    int col = (int)(idx % 2560);
    int row = (int)(idx / 2560);
    int ol = row & 127, b = row >> 7;
    int ic = col / 5, kk = col % 5;
    int l = 2 * ol - 2 + kk;
    patch[idx] = (l >= 0 && l < 256) ? c1[((size_t)b * 256 + l) * 512 + ic] : 0.f;
}

__global__ void xpose_bt(const float* __restrict__ c2, float* __restrict__ xtbc)
{
    int idx = blockIdx.x * 256 + threadIdx.x;
    if (idx >= 4096 * 512) return;
    int c = idx & 511;
    int row = idx >> 9;
    int t = row >> 5, b = row & 31;
    xtbc[idx] = c2[((size_t)b * 128 + t) * 512 + c];
}

// ---------------- persistent encoder (validated body) ------------------------
__global__ __launch_bounds__(256) void encoder_loop_k(
    const float* __restrict__ gif, const float* __restrict__ gib,
    const float* __restrict__ WhhF, const float* __restrict__ WhhB,
    const float* __restrict__ bhhF, const float* __restrict__ bhhB,
    float* __restrict__ encout, float* __restrict__ comb, float* __restrict__ hbuf)
{
    __shared__ float As[32][17];
    __shared__ float Bs[3][32][17];
    const int tid = threadIdx.x;
    const int bid = blockIdx.x;
    const int NB  = gridDim.x;

    for (int i = bid * 256 + tid; i < 32768; i += NB * 256) hbuf[i] = 0.f;
    grid_barrier();

    for (int t = 0; t < 128; t++) {
        for (int job = bid; job < 32; job += NB) {
            const int dir = job >> 4;
            const int j0  = (job & 15) * 32;
            const float* Whh = dir ? WhhB : WhhF;
            const float* bhh = dir ? bhhB : bhhF;
            const float* giB = dir ? gib : gif;
            const int tx = tid & 31;
            const int ty = tid >> 5;
            const int j  = j0 + tx;

            const float* hin  = hbuf + (t & 1) * 32768 + dir * 16384;
            float*       hout = hbuf + ((t + 1) & 1) * 32768 + dir * 16384;

            float acc[3][4] = {{0,0,0,0},{0,0,0,0},{0,0,0,0}};

            for (int k0 = 0; k0 < 512; k0 += 16) {
                {
                    int m = tid >> 4, kk = tid & 15;
                    As[m][kk] = hin[m * 512 + k0 + kk];
                    int e = tid + 256; m = e >> 4; kk = e & 15;
                    As[m][kk] = hin[m * 512 + k0 + kk];
                }
#pragma unroll
                for (int i = 0; i < 6; i++) {
                    int e = tid + i * 256;
                    int g = e >> 9, rest = e & 511;
                    int n = rest >> 4, kk = rest & 15;
                    Bs[g][n][kk] = Whh[(size_t)(g * 512 + j0 + n) * 512 + k0 + kk];
                }
                __syncthreads();
#pragma unroll
                for (int kk = 0; kk < 16; kk++) {
                    float b0 = Bs[0][tx][kk], b1 = Bs[1][tx][kk], b2 = Bs[2][tx][kk];
#pragma unroll
                    for (int r = 0; r < 4; r++) {
                        float a = As[ty * 4 + r][kk];
                        acc[0][r] = fmaf(a, b0, acc[0][r]);
                        acc[1][r] = fmaf(a, b1, acc[1][r]);
                        acc[2][r] = fmaf(a, b2, acc[2][r]);
                    }
                }
                __syncthreads();
            }

            const int ts = dir ? (127 - t) : t;
            const float* gi = giB + (size_t)ts * 32 * 1536;
            const float b_r = bhh[j], b_z = bhh[512 + j], b_n = bhh[1024 + j];
#pragma unroll
            for (int r = 0; r < 4; r++) {
                int m = ty * 4 + r;
                float ir = gi[m * 1536 + j], iz = gi[m * 1536 + 512 + j], in = gi[m * 1536 + 1024 + j];
                float rr = 1.f / (1.f + expf(-(ir + acc[0][r] + b_r)));
                float zz = 1.f / (1.f + expf(-(iz + acc[1][r] + b_z)));
                float nn = tanhf(in + rr * (acc[2][r] + b_n));
                float hv = (1.f - zz) * nn + zz * hin[m * 512 + j];
                hout[m * 512 + j] = hv;
                encout[((size_t)m * 128 + ts) * 1024 + dir * 512 + j] = hv;
            }
            __syncthreads();
        }
        grid_barrier();
    }

    for (int i = bid * 256 + tid; i < 32 * 1024; i += NB * 256) {
        int b = i >> 10, jj = i & 1023;
        comb[i] = (jj < 512) ? hbuf[b * 512 + jj] : hbuf[16384 + b * 512 + (jj - 512)];
    }
}

// ---------------- persistent decoder with overlapped windows -----------------
__global__ __launch_bounds__(256) void decoder_loop_k(
    float* __restrict__ S,
    const float* __restrict__ emb, const float* __restrict__ attn_Wd,
    const float* __restrict__ attn_v,
    const float* __restrict__ Wih0, const float* __restrict__ Whh0,
    const float* __restrict__ bih0, const float* __restrict__ bhh0,
    const float* __restrict__ Wih1, const float* __restrict__ Whh1,
    const float* __restrict__ bih1, const float* __restrict__ bhh1,
    const float* __restrict__ projW, const float* __restrict__ projb,
    const float* __restrict__ bridgeW, const float* __restrict__ bridgeb,
    float* __restrict__ out)
{
    __shared__ float As16[16][65];
    __shared__ float Bs16[16][65];
    __shared__ float As32[32][17];
    __shared__ float Bs64[64][17];
    __shared__ float sacc[32][65];
    __shared__ float s_h[512];
    __shared__ float s_dq[512];
    __shared__ float s_sc[128];
    __shared__ float s_red[256];
    __shared__ float sv[256];
    __shared__ int   si[256];

    const int tid = threadIdx.x;
    const int bid = blockIdx.x;
    const int NB  = gridDim.x;
    const int lane = tid & 31, warp = tid >> 5;
    const int tx = tid & 15, ty = tid >> 4;

    const float* encout  = S + OFF_ENCOUT;
    const float* encproj = S + OFF_ENCPROJ;
    const float* comb    = S + OFF_COMB;
    float* bridge = S + OFF_BRIDGE;
    float* h0buf  = S + OFF_H0BUF;
    float* h1buf  = S + OFF_H1BUF;
    float* ctx    = S + OFF_CTX;
    float* logits = S + OFF_LOGITS;
    float* gbuf   = S + OFF_GBUF;
    float* gbuf1  = S + OFF_GBUF1;
    int*   tok    = (int*)(S + OFF_TOK);

    // ---- prologue ----
    for (int i = bid * 256 + tid; i < 32 * 1024; i += NB * 256) {
        int b = i >> 10, n = i & 1023;
        const float* a = comb + b * 1024;
        const float* w = bridgeW + (size_t)n * 1024;
        float s = bridgeb[n];
        for (int k = 0; k < 1024; k++) s = fmaf(a[k], w[k], s);
        bridge[i] = s;
    }
    grid_barrier();
    for (int i = bid * 256 + tid; i < 32 * 1024; i += NB * 256) {
        int b = i >> 10, j = i & 1023;
        float v = bridge[i];
        if (j < 512) h0buf[b * 512 + j] = v; else h1buf[b * 512 + (j - 512)] = v;
    }
    if (bid == 0 && tid < 32) { tok[tid] = 1; out[tid * MAXDEC] = 1.0f; }
    grid_barrier();

    for (int s = 0; s < NSTEPS; s++) {
        const int p = s & 1, q = 1 - p;
        const float* h0in = h0buf + p * 16384;
        float*       h0out = h0buf + q * 16384;
        const float* h1in = h1buf + p * 16384;
        float*       h1out = h1buf + q * 16384;

        // ==== W1: attention (0..31) || gates0 partial emb+h0 (32..63)
        //          || gates1 h-part (64..95)
        for (int job = bid; job < 96; job += NB) {
            if (job < 32) {
                int b = job;
                for (int i = tid; i < 512; i += 256) s_h[i] = h1in[b * 512 + i];
                __syncthreads();
                for (int a = warp; a < 512; a += 8) {
                    const float* wr = attn_Wd + (size_t)a * 512;
                    float acc = 0.f;
                    for (int k = lane; k < 512; k += 32) acc = fmaf(s_h[k], wr[k], acc);
#pragma unroll
                    for (int o = 16; o; o >>= 1) acc += __shfl_xor_sync(0xffffffffu, acc, o);
                    if (lane == 0) s_dq[a] = acc;
                }
                __syncthreads();
                for (int t = warp; t < 128; t += 8) {
                    const float* ep = encproj + ((size_t)b * 128 + t) * 512;
                    float acc = 0.f;
                    for (int a = lane; a < 512; a += 32)
                        acc = fmaf(tanhf(ep[a] + s_dq[a]), attn_v[a], acc);
#pragma unroll
                    for (int o = 16; o; o >>= 1) acc += __shfl_xor_sync(0xffffffffu, acc, o);
                    if (lane == 0) s_sc[t] = acc;
                }
                __syncthreads();
                float mv = (tid < 128) ? s_sc[tid] : -INFINITY;
                s_red[tid] = mv; __syncthreads();
                for (int o = 128; o; o >>= 1) {
                    if (tid < o) s_red[tid] = fmaxf(s_red[tid], s_red[tid + o]);
                    __syncthreads();
                }
                float mx = s_red[0]; __syncthreads();
                float ev = (tid < 128) ? expf(s_sc[tid] - mx) : 0.f;
                s_red[tid] = ev; __syncthreads();
                for (int o = 128; o; o >>= 1) {
                    if (tid < o) s_red[tid] += s_red[tid + o];
                    __syncthreads();
                }
                float dn = s_red[0]; __syncthreads();
                if (tid < 128) s_sc[tid] = ev / dn;
                __syncthreads();
                for (int j = tid; j < 1024; j += 256) {
                    const float* eo = encout + (size_t)b * 131072 + j;
                    float acc = 0.f;
#pragma unroll 4
                    for (int t = 0; t < 128; t++) acc = fmaf(s_sc[t], eo[(size_t)t * 1024], acc);
                    ctx[b * 1024 + j] = acc;
                }
                __syncthreads();
            } else if (job < 64) {
                // gates0 partial: K over {emb 0..511, h0 1536..2047}
                const int jobx = job - 32;
                const int j0 = jobx * 16;
                float acc[2][4] = {{0,0,0,0},{0,0,0,0}};
                for (int kb = 0; kb < 1024; kb += 16) {
                    const int k0 = (kb < 512) ? kb : (kb + 1024);
#pragma unroll
                    for (int rep = 0; rep < 2; rep++) {
                        int e = tid + rep * 256;
                        int m = e >> 4, kk = e & 15;
                        int k = k0 + kk;
                        float av;
                        if (k < 512) {
                            int tk = tok[m];
                            if (tk < 0) tk = 0;
                            if (tk >= VOCAB) tk = VOCAB - 1;
                            av = emb[(size_t)tk * 512 + k];
                        } else av = h0in[m * 512 + (k - 1536)];
                        As32[m][kk] = av;
                    }
#pragma unroll
                    for (int i = 0; i < 4; i++) {
                        int e = tid + i * 256;
                        int c = e >> 4, kk = e & 15;
                        int k = k0 + kk;
                        int g = c >> 4, jj = c & 15;
                        float bv;
                        if (g < 2) {
                            int row = g * 512 + j0 + jj;
                            bv = (k < 1536) ? Wih0[(size_t)row * 1536 + k]
                                            : Whh0[(size_t)row * 512 + (k - 1536)];
                        } else if (g == 2) {
                            int row = 1024 + j0 + jj;
                            bv = (k < 1536) ? Wih0[(size_t)row * 1536 + k] : 0.f;
                        } else {
                            int row = 1024 + j0 + jj;
                            bv = (k >= 1536) ? Whh0[(size_t)row * 512 + (k - 1536)] : 0.f;
                        }
                        Bs64[c][kk] = bv;
                    }
                    __syncthreads();
#pragma unroll
                    for (int kk = 0; kk < 16; kk++) {
                        float a0 = As32[ty * 2][kk], a1 = As32[ty * 2 + 1][kk];
#pragma unroll
                        for (int cc = 0; cc < 4; cc++) {
                            float bv = Bs64[tx + 16 * cc][kk];
                            acc[0][cc] = fmaf(a0, bv, acc[0][cc]);
                            acc[1][cc] = fmaf(a1, bv, acc[1][cc]);
                        }
                    }
                    __syncthreads();
                }
#pragma unroll
                for (int rep = 0; rep < 2; rep++)
#pragma unroll
                    for (int cc = 0; cc < 4; cc++)
                        gbuf[(ty * 2 + rep) * 2048 + jobx * 64 + tx + 16 * cc] = acc[rep][cc];
                __syncthreads();
            } else {
                // gates1 h-part: K=512 over h1in
                const int jobx = job - 64;
                const int j0 = jobx * 16;
                float acc[2][4] = {{0,0,0,0},{0,0,0,0}};
                for (int k0 = 0; k0 < 512; k0 += 16) {
#pragma unroll
                    for (int rep = 0; rep < 2; rep++) {
                        int e = tid + rep * 256;
                        int m = e >> 4, kk = e & 15;
                        As32[m][kk] = h1in[m * 512 + k0 + kk];
                    }
#pragma unroll
                    for (int i = 0; i < 4; i++) {
                        int e = tid + i * 256;
                        int c = e >> 4, kk = e & 15;
                        int k = k0 + kk;
                        int g = c >> 4, jj = c & 15;
                        float bv;
                        if (g < 2) {
                            int row = g * 512 + j0 + jj;
                            bv = Whh1[(size_t)row * 512 + k];
                        } else if (g == 3) {
                            int row = 1024 + j0 + jj;
                            bv = Whh1[(size_t)row * 512 + k];
                        } else bv = 0.f;
                        Bs64[c][kk] = bv;
                    }
                    __syncthreads();
#pragma unroll
                    for (int kk = 0; kk < 16; kk++) {
                        float a0 = As32[ty * 2][kk], a1 = As32[ty * 2 + 1][kk];
#pragma unroll
                        for (int cc = 0; cc < 4; cc++) {
                            float bv = Bs64[tx + 16 * cc][kk];
                            acc[0][cc] = fmaf(a0, bv, acc[0][cc]);
                            acc[1][cc] = fmaf(a1, bv, acc[1][cc]);
                        }
                    }
                    __syncthreads();
                }
#pragma unroll
                for (int rep = 0; rep < 2; rep++)
#pragma unroll
                    for (int cc = 0; cc < 4; cc++)
                        gbuf1[(ty * 2 + rep) * 2048 + jobx * 64 + tx + 16 * cc] = acc[rep][cc];
                __syncthreads();
            }
        }
        grid_barrier();

        // ==== W2: gates0 finalize (ctx K, 0..31) || logits-ctx (32..156)
        for (int job = bid; job < 157; job += NB) {
            if (job < 32) {
                const int j0 = job * 16;
                float acc[2][4];
#pragma unroll
                for (int rep = 0; rep < 2; rep++)
#pragma unroll
                    for (int cc = 0; cc < 4; cc++)
                        acc[rep][cc] = gbuf[(ty * 2 + rep) * 2048 + job * 64 + tx + 16 * cc];
                for (int k0 = 512; k0 < 1536; k0 += 16) {
#pragma unroll
                    for (int rep = 0; rep < 2; rep++) {
                        int e = tid + rep * 256;
                        int m = e >> 4, kk = e & 15;
                        As32[m][kk] = ctx[m * 1024 + (k0 + kk - 512)];
                    }
#pragma unroll
                    for (int i = 0; i < 4; i++) {
                        int e = tid + i * 256;
                        int c = e >> 4, kk = e & 15;
                        int k = k0 + kk;
                        int g = c >> 4, jj = c & 15;
                        float bv;
                        if (g < 2) {
                            int row = g * 512 + j0 + jj;
                            bv = Wih0[(size_t)row * 1536 + k];
                        } else if (g == 2) {
                            int row = 1024 + j0 + jj;
                            bv = Wih0[(size_t)row * 1536 + k];
                        } else bv = 0.f;
                        Bs64[c][kk] = bv;
                    }
                    __syncthreads();
#pragma unroll
                    for (int kk = 0; kk < 16; kk++) {
                        float a0 = As32[ty * 2][kk], a1 = As32[ty * 2 + 1][kk];
#pragma unroll
                        for (int cc = 0; cc < 4; cc++) {
                            float bv = Bs64[tx + 16 * cc][kk];
                            acc[0][cc] = fmaf(a0, bv, acc[0][cc]);
                            acc[1][cc] = fmaf(a1, bv, acc[1][cc]);
                        }
                    }
                    __syncthreads();
                }
#pragma unroll
                for (int rep = 0; rep < 2; rep++)
#pragma unroll
                    for (int cc = 0; cc < 4; cc++)
                        sacc[ty * 2 + rep][tx + 16 * cc] = acc[rep][cc];
                __syncthreads();
                for (int i = tid; i < 512; i += 256) {
                    int b = i >> 4, jj = i & 15;
                    int j = j0 + jj;
                    float r_  = sacc[b][jj]      + bih0[j]        + bhh0[j];
                    float z_  = sacc[b][16 + jj] + bih0[512 + j]  + bhh0[512 + j];
                    float in_ = sacc[b][32 + jj] + bih0[1024 + j];
                    float hn_ = sacc[b][48 + jj] + bhh0[1024 + j];
                    float rr = 1.f / (1.f + expf(-r_));
                    float zz = 1.f / (1.f + expf(-z_));
                    float nn = tanhf(in_ + rr * hn_);
                    h0out[b * 512 + j] = (1.f - zz) * nn + zz * h0in[b * 512 + j];
                }
                __syncthreads();
            } else {
                const int n0 = (job - 32) * 64;
                float acc[2][4] = {{0,0,0,0},{0,0,0,0}};
                for (int k0 = 512; k0 < 1536; k0 += 16) {
#pragma unroll
                    for (int r = 0; r < 4; r++) {
                        int i  = tid + r * 256;
                        int mm = i >> 4, kk = i & 15;
                        int k = k0 + kk;
                        As16[kk][mm] = (mm < 32) ? ctx[mm * 1024 + (k - 512)] : 0.f;
                        Bs16[kk][mm] = projW[(size_t)(n0 + mm) * 1536 + k];
                    }
                    __syncthreads();
#pragma unroll
                    for (int kk = 0; kk < 16; kk++) {
                        float a0 = As16[kk][ty], a1 = As16[kk][ty + 16];
#pragma unroll
                        for (int j = 0; j < 4; j++) {
                            float bv = Bs16[kk][tx + 16 * j];
                            acc[0][j] = fmaf(a0, bv, acc[0][j]);
                            acc[1][j] = fmaf(a1, bv, acc[1][j]);
                        }
                    }
                    __syncthreads();
                }
#pragma unroll
                for (int i = 0; i < 2; i++) {
                    int m = ty + 16 * i;
#pragma unroll
                    for (int j = 0; j < 4; j++) {
                        int n = n0 + tx + 16 * j;
                        logits[(size_t)m * VOCAB + n] = acc[i][j] + projb[n];
                    }
                }
                __syncthreads();
            }
        }
        grid_barrier();

        // ==== W3: gates1 finalize — x-part only (K=512 over h0out), 32 jobs
        for (int job = bid; job < 32; job += NB) {
            const int j0 = job * 16;
            float acc[2][4];
#pragma unroll
            for (int rep = 0; rep < 2; rep++)
#pragma unroll
                for (int cc = 0; cc < 4; cc++)
                    acc[rep][cc] = gbuf1[(ty * 2 + rep) * 2048 + job * 64 + tx + 16 * cc];
            for (int k0 = 0; k0 < 512; k0 += 16) {
#pragma unroll
                for (int rep = 0; rep < 2; rep++) {
                    int e = tid + rep * 256;
                    int m = e >> 4, kk = e & 15;
                    As32[m][kk] = h0out[m * 512 + k0 + kk];
                }
#pragma unroll
                for (int i = 0; i < 4; i++) {
                    int e = tid + i * 256;
                    int c = e >> 4, kk = e & 15;
                    int k = k0 + kk;
                    int g = c >> 4, jj = c & 15;
                    float bv;
                    if (g < 2) {
                        int row = g * 512 + j0 + jj;
                        bv = Wih1[(size_t)row * 512 + k];
                    } else if (g == 2) {
                        int row = 1024 + j0 + jj;
                        bv = Wih1[(size_t)row * 512 + k];
                    } else bv = 0.f;
                    Bs64[c][kk] = bv;
                }
                __syncthreads();
#pragma unroll
                for (int kk = 0; kk < 16; kk++) {
                    float a0 = As32[ty * 2][kk], a1 = As32[ty * 2 + 1][kk];
#pragma unroll
                    for (int cc = 0; cc < 4; cc++) {
                        float bv = Bs64[tx + 16 * cc][kk];
                        acc[0][cc] = fmaf(a0, bv, acc[0][cc]);
                        acc[1][cc] = fmaf(a1, bv, acc[1][cc]);
                    }
                }
                __syncthreads();
            }
#pragma unroll
            for (int rep = 0; rep < 2; rep++)
#pragma unroll
                for (int cc = 0; cc < 4; cc++)
                    sacc[ty * 2 + rep][tx + 16 * cc] = acc[rep][cc];
            __syncthreads();
            for (int i = tid; i < 512; i += 256) {
                int b = i >> 4, jj = i & 15;
                int j = j0 + jj;
                float r_  = sacc[b][jj]      + bih1[j]        + bhh1[j];
                float z_  = sacc[b][16 + jj] + bih1[512 + j]  + bhh1[512 + j];
                float in_ = sacc[b][32 + jj] + bih1[1024 + j];
                float hn_ = sacc[b][48 + jj] + bhh1[1024 + j];
                float rr = 1.f / (1.f + expf(-r_));
                float zz = 1.f / (1.f + expf(-z_));
                float nn = tanhf(in_ + rr * hn_);
                h1out[b * 512 + j] = (1.f - zz) * nn + zz * h1in[b * 512 + j];
            }
            __syncthreads();
        }
        grid_barrier();

        // ==== W4: logits += h1 part (K=512), 125 jobs
        for (int job = bid; job < 125; job += NB) {
            const int n0 = job * 64;
            float acc[2][4] = {{0,0,0,0},{0,0,0,0}};
            for (int k0 = 0; k0 < 512; k0 += 16) {
#pragma unroll
                for (int r = 0; r < 4; r++) {
                    int i  = tid + r * 256;
                    int mm = i >> 4, kk = i & 15;
                    int k = k0 + kk;
                    As16[kk][mm] = (mm < 32) ? h1out[mm * 512 + k] : 0.f;
                    Bs16[kk][mm] = projW[(size_t)(n0 + mm) * 1536 + k];
                }
                __syncthreads();
#pragma unroll
                for (int kk = 0; kk < 16; kk++) {
                    float a0 = As16[kk][ty], a1 = As16[kk][ty + 16];
#pragma unroll
                    for (int j = 0; j < 4; j++) {
                        float bv = Bs16[kk][tx + 16 * j];
                        acc[0][j] = fmaf(a0, bv, acc[0][j]);
                        acc[1][j] = fmaf(a1, bv, acc[1][j]);
                    }
                }
                __syncthreads();
            }
#pragma unroll
            for (int i = 0; i < 2; i++) {
                int m = ty + 16 * i;
#pragma unroll
                for (int j = 0; j < 4; j++) {
                    int n = n0 + tx + 16 * j;
                    logits[(size_t)m * VOCAB + n] += acc[i][j];
                }
            }
            __syncthreads();
        }
        grid_barrier();

        // ==== W5: argmax, 32 jobs
        for (int b = bid; b < 32; b += NB) {
            float best = -INFINITY; int bi = SENTINEL;
            for (int i = tid; i < VOCAB; i += 256) {
                float v = logits[(size_t)b * VOCAB + i];
                if (v > best) { best = v; bi = i; }
            }
            sv[tid] = best; si[tid] = bi; __syncthreads();
            for (int o = 128; o; o >>= 1) {
                if (tid < o) {
                    if (sv[tid + o] > sv[tid] ||
                        (sv[tid + o] == sv[tid] && si[tid + o] < si[tid])) {
                        sv[tid] = sv[tid + o]; si[tid] = si[tid + o];
                    }
                }
                __syncthreads();
            }
            if (tid == 0) { tok[b] = si[0]; out[b * MAXDEC + s + 1] = (float)si[0]; }
            __syncthreads();
        }
        grid_barrier();
    }
}

// ---------------- host ----------------
static inline unsigned cdiv(unsigned a, unsigned b) { return (a + b - 1) / b; }

static void gemm(const float* A, const float* Bm, const float* bias, float* C,
                 int M, int N, int K, int relu)
{
    dim3 grid(cdiv(M, 64), cdiv(N, 64));
    gemm_abt<<<grid, 256>>>(A, Bm, bias, C, M, N, K, relu);
}

enum {
    I_FEAT, I_CW1, I_CB1, I_CW2, I_CB2,
    I_EWIHF, I_EWHHF, I_EBIHF, I_EBHHF,
    I_EWIHB, I_EWHHB, I_EBIHB, I_EBHHB,
    I_BRW, I_BRB, I_EMB, I_AWE, I_AWD, I_AV,
    I_DWIH0, I_DWHH0, I_DBIH0, I_DBHH0,
    I_DWIH1, I_DWHH1, I_DBIH1, I_DBHH1,
    I_PW, I_PB, N_LOGICAL
};

extern "C" void kernel_launch(void* const* d_in, const int* in_sizes, int n_in,
                              void* d_out, int out_size)
{
    (void)out_size;
    static const int posA[N_LOGICAL] = {
        0, 1, 2, 3, 4,  5, 6, 7, 8,  9, 10, 11, 12,
        13, 14, 15, 16, 17, 18,  19, 20, 21, 22,  23, 24, 25, 26,  27, 28 };
    static const int posB[N_LOGICAL] = {
        26, 7, 5, 8, 6,  21, 19, 25, 23,  20, 18, 24, 22,
        3, 4, 17, 1, 0, 2,  11, 9, 15, 13,  12, 10, 16, 14,  27, 28 };
    static const long long esz[N_LOGICAL] = {
        4194304, 655360, 512, 1310720, 512,
        786432, 786432, 1536, 1536,  786432, 786432, 1536, 1536,
        1048576, 1024, 4096000, 524288, 262144, 512,
        2359296, 786432, 1536, 1536,  786432, 786432, 1536, 1536,
        12288000, 8000 };

    const int* pos = posA;
    if (n_in >= N_LOGICAL && in_sizes) {
        int misB = 0;
        for (int i = 0; i < N_LOGICAL; i++)
            if ((long long)in_sizes[posB[i]] != esz[i]) misB++;
        if (misB == 0) {
            int misA = 0;
            for (int i = 0; i < N_LOGICAL; i++)
                if ((long long)in_sizes[posA[i]] != esz[i]) misA++;
            if (misA > 0) pos = posB;
        }
    }

    const float* features = (const float*)d_in[pos[I_FEAT]];
    const float* conv_w1  = (const float*)d_in[pos[I_CW1]];
    const float* conv_b1  = (const float*)d_in[pos[I_CB1]];
    const float* conv_w2  = (const float*)d_in[pos[I_CW2]];
    const float* conv_b2  = (const float*)d_in[pos[I_CB2]];
    const float* Wih_f    = (const float*)d_in[pos[I_EWIHF]];
    const float* Whh_f    = (const float*)d_in[pos[I_EWHHF]];
    const float* bih_f    = (const float*)d_in[pos[I_EBIHF]];
    const float* bhh_f    = (const float*)d_in[pos[I_EBHHF]];
    const float* Wih_b    = (const float*)d_in[pos[I_EWIHB]];
    const float* Whh_b    = (const float*)d_in[pos[I_EWHHB]];
    const float* bih_b    = (const float*)d_in[pos[I_EBIHB]];
    const float* bhh_b    = (const float*)d_in[pos[I_EBHHB]];
    const float* bridge_W = (const float*)d_in[pos[I_BRW]];
    const float* bridge_b = (const float*)d_in[pos[I_BRB]];
    const float* emb      = (const float*)d_in[pos[I_EMB]];
    const float* attn_We  = (const float*)d_in[pos[I_AWE]];
    const float* attn_Wd  = (const float*)d_in[pos[I_AWD]];
    const float* attn_v   = (const float*)d_in[pos[I_AV]];
    const float* dWih0    = (const float*)d_in[pos[I_DWIH0]];
    const float* dWhh0    = (const float*)d_in[pos[I_DWHH0]];
    const float* dbih0    = (const float*)d_in[pos[I_DBIH0]];
    const float* dbhh0    = (const float*)d_in[pos[I_DBHH0]];
    const float* dWih1    = (const float*)d_in[pos[I_DWIH1]];
    const float* dWhh1    = (const float*)d_in[pos[I_DWHH1]];
    const float* dbih1    = (const float*)d_in[pos[I_DBIH1]];
    const float* dbhh1    = (const float*)d_in[pos[I_DBHH1]];
    const float* proj_W   = (const float*)d_in[pos[I_PW]];
    const float* proj_b   = (const float*)d_in[pos[I_PB]];
    float* out = (float*)d_out;

    float* S = nullptr;
    cudaGetSymbolAddress((void**)&S, g_scratch);

    float* patch   = S + OFF_PATCH;
    float* c1      = S + OFF_C1;
    float* c2      = S + OFF_C2;
    float* xtbc    = S + OFF_XTBC;
    float* gif     = S + OFF_GIF;
    float* gib     = S + OFF_GIB;
    float* encout  = S + OFF_ENCOUT;
    float* encproj = S + OFF_ENCPROJ;
    float* hbuf    = S + OFF_HBUF;
    float* comb    = S + OFF_COMB;

    int dev = 0; cudaGetDevice(&dev);
    int nsm = 0; cudaDeviceGetAttribute(&nsm, cudaDevAttrMultiProcessorCount, dev);
    if (nsm <= 0) nsm = 1;
    int occE = 0, occD = 0;
    cudaOccupancyMaxActiveBlocksPerMultiprocessor(&occE, encoder_loop_k, 256, 0);
    cudaOccupancyMaxActiveBlocksPerMultiprocessor(&occD, decoder_loop_k, 256, 0);
    if (occE < 1) occE = 1;
    if (occD < 1) occD = 1;
    long long ecap = (long long)nsm * occE;
    long long dcap = (long long)nsm * occD;
    int enc_blk = (int)(ecap < 32  ? ecap : 32);
    int dec_blk = (int)(dcap < 157 ? dcap : 157);

    im2col1<<<cdiv(8192u * 1280u, 256u), 256>>>(features, patch);
    gemm(patch, conv_w1, conv_b1, c1, 8192, 512, 1280, 1);
    im2col2<<<cdiv(4096u * 2560u, 256u), 256>>>(c1, patch);
    gemm(patch, conv_w2, conv_b2, c2, 4096, 512, 2560, 1);
    xpose_bt<<<cdiv(4096u * 512u, 256u), 256>>>(c2, xtbc);

    gemm(xtbc, Wih_f, bih_f, gif, 4096, 1536, 512, 0);
    gemm(xtbc, Wih_b, bih_b, gib, 4096, 1536, 512, 0);

    encoder_loop_k<<<enc_blk, 256>>>(gif, gib, Whh_f, Whh_b, bhh_f, bhh_b,
                                     encout, comb, hbuf);

    gemm(encout, attn_We, nullptr, encproj, 4096, 512, 1024, 0);

    decoder_loop_k<<<dec_blk, 256>>>(S, emb, attn_Wd, attn_v,
                                     dWih0, dWhh0, dbih0, dbhh0,
                                     dWih1, dWhh1, dbih1, dbhh1,
                                     proj_W, proj_b, bridge_W, bridge_b, out);
}

// round 16
// speedup vs baseline: 2.0618x; 1.1498x over previous
#include <cuda_runtime.h>
#include <math.h>

#define VOCAB  8000
#define MAXDEC 50
#define NSTEPS 49
#define SENTINEL 7777

// ---------------- scratch layout (floats) ----------------
#define OFF_PATCH    0ull            // 8192*1280
#define OFF_C1       10485760ull     // 8192*512
#define OFF_C2       14680064ull     // 4096*512
#define OFF_XTBC     16777216ull     // 4096*512
#define OFF_GIF      18874368ull     // 4096*1536
#define OFF_GIB      25165824ull     // 4096*1536
#define OFF_ENCOUT   31457280ull     // 32*128*1024
#define OFF_ENCPROJ  35651584ull     // 32*128*512
#define OFF_HBUF     37748736ull     // 2*2*32*512
#define OFF_COMB     37814272ull     // 32*1024
#define OFF_BRIDGE   37847040ull     // 32*1024
#define OFF_H0BUF    37879808ull     // 2*32*512
#define OFF_H1BUF    37912576ull     // 2*32*512
#define OFF_CTX      37945344ull     // 32*1024
#define OFF_LOGITS   37978112ull     // 32*8000
#define OFF_GBUF     38234112ull     // 32*2048 gates0 partial
#define OFF_GBUF1    38299648ull     // 32*2048 gates1 h-part partial
#define OFF_TOK      38365184ull     // 32 ints
#define SCRATCH_FLOATS 38365248ull

static __device__ float g_scratch[SCRATCH_FLOATS];

// ---------------- software grid barrier (volatile-poll release) --------------
__device__ unsigned g_bar_cnt = 0;
__device__ unsigned g_bar_gen = 0;

__device__ __forceinline__ void grid_barrier()
{
    unsigned nblk = gridDim.x;
    __threadfence();
    __syncthreads();
    if (threadIdx.x == 0) {
        unsigned gen = *(volatile unsigned*)&g_bar_gen;
        if (atomicAdd(&g_bar_cnt, 1u) == nblk - 1u) {
            atomicExch(&g_bar_cnt, 0u);
            __threadfence();
            *(volatile unsigned*)&g_bar_gen = gen + 1u;
        } else {
            while (*(volatile unsigned*)&g_bar_gen == gen) __nanosleep(32);
        }
    }
    __syncthreads();
    __threadfence();
}

// ---------------- standalone GEMM (strided conflict-free tile) ---------------
__global__ void gemm_abt(const float* __restrict__ A, const float* __restrict__ Bm,
                         const float* __restrict__ bias, float* __restrict__ C,
                         int M, int N, int K, int relu)
{
    __shared__ float As[16][65];
    __shared__ float Bs[16][65];
    int tid = threadIdx.x;
    int tx = tid & 15, ty = tid >> 4;
    int m0 = blockIdx.x * 64, n0 = blockIdx.y * 64;
    float acc[4][4];
#pragma unroll
    for (int i = 0; i < 4; i++)
#pragma unroll
        for (int j = 0; j < 4; j++) acc[i][j] = 0.f;

    for (int k0 = 0; k0 < K; k0 += 16) {
#pragma unroll
        for (int r = 0; r < 4; r++) {
            int i  = tid + r * 256;
            int mm = i >> 4, kk = i & 15;
            As[kk][mm] = (m0 + mm < M) ? A[(size_t)(m0 + mm) * K + k0 + kk] : 0.f;
            Bs[kk][mm] = (n0 + mm < N) ? Bm[(size_t)(n0 + mm) * K + k0 + kk] : 0.f;
        }
        __syncthreads();
#pragma unroll
        for (int kk = 0; kk < 16; kk++) {
            float a[4], b[4];
#pragma unroll
            for (int i = 0; i < 4; i++) a[i] = As[kk][ty + 16 * i];
#pragma unroll
            for (int j = 0; j < 4; j++) b[j] = Bs[kk][tx + 16 * j];
#pragma unroll
            for (int i = 0; i < 4; i++)
#pragma unroll
                for (int j = 0; j < 4; j++) acc[i][j] = fmaf(a[i], b[j], acc[i][j]);
        }
        __syncthreads();
    }
#pragma unroll
    for (int i = 0; i < 4; i++) {
        int m = m0 + ty + 16 * i;
        if (m >= M) continue;
#pragma unroll
        for (int j = 0; j < 4; j++) {
            int n = n0 + tx + 16 * j;
            if (n >= N) continue;
            float v = acc[i][j] + (bias ? bias[n] : 0.f);
            if (relu) v = fmaxf(v, 0.f);
            C[(size_t)m * N + n] = v;
        }
    }
}

// ---------------- conv im2col / transpose ----------------
__global__ void im2col1(const float* __restrict__ f, float* __restrict__ patch)
{
    long long idx = (long long)blockIdx.x * 256 + threadIdx.x;
    if (idx >= 8192LL * 1280) return;
    int col = (int)(idx % 1280);
    int row = (int)(idx / 1280);
    int ol = row & 255, b = row >> 8;
    int ic = col / 5, kk = col % 5;
    int l = 2 * ol - 2 + kk;
    patch[idx] = (l >= 0 && l < 512) ? f[((size_t)b * 512 + l) * 256 + ic] : 0.f;
}

__global__ void im2col2(const float* __restrict__ c1, float* __restrict__ patch)
{
    long long idx = (long long)blockIdx.x * 256 + threadIdx.x;
    if (idx >= 4096LL * 2560) return;
    int col = (int)(idx % 2560);
    int row = (int)(idx / 2560);
    int ol = row & 127, b = row >> 7;
    int ic = col / 5, kk = col % 5;
    int l = 2 * ol - 2 + kk;
    patch[idx] = (l >= 0 && l < 256) ? c1[((size_t)b * 256 + l) * 512 + ic] : 0.f;
}

__global__ void xpose_bt(const float* __restrict__ c2, float* __restrict__ xtbc)
{
    int idx = blockIdx.x * 256 + threadIdx.x;
    if (idx >= 4096 * 512) return;
    int c = idx & 511;
    int row = idx >> 9;
    int t = row >> 5, b = row & 31;
    xtbc[idx] = c2[((size_t)b * 128 + t) * 512 + c];
}

// ---------------- persistent encoder (validated body) ------------------------
__global__ __launch_bounds__(256) void encoder_loop_k(
    const float* __restrict__ gif, const float* __restrict__ gib,
    const float* __restrict__ WhhF, const float* __restrict__ WhhB,
    const float* __restrict__ bhhF, const float* __restrict__ bhhB,
    float* __restrict__ encout, float* __restrict__ comb, float* __restrict__ hbuf)
{
    __shared__ float As[32][17];
    __shared__ float Bs[3][32][17];
    const int tid = threadIdx.x;
    const int bid = blockIdx.x;
    const int NB  = gridDim.x;

    for (int i = bid * 256 + tid; i < 32768; i += NB * 256) hbuf[i] = 0.f;
    grid_barrier();

    for (int t = 0; t < 128; t++) {
        for (int job = bid; job < 32; job += NB) {
            const int dir = job >> 4;
            const int j0  = (job & 15) * 32;
            const float* Whh = dir ? WhhB : WhhF;
            const float* bhh = dir ? bhhB : bhhF;
            const float* giB = dir ? gib : gif;
            const int tx = tid & 31;
            const int ty = tid >> 5;
            const int j  = j0 + tx;

            const float* hin  = hbuf + (t & 1) * 32768 + dir * 16384;
            float*       hout = hbuf + ((t + 1) & 1) * 32768 + dir * 16384;

            float acc[3][4] = {{0,0,0,0},{0,0,0,0},{0,0,0,0}};

            for (int k0 = 0; k0 < 512; k0 += 16) {
                {
                    int m = tid >> 4, kk = tid & 15;
                    As[m][kk] = hin[m * 512 + k0 + kk];
                    int e = tid + 256; m = e >> 4; kk = e & 15;
                    As[m][kk] = hin[m * 512 + k0 + kk];
                }
#pragma unroll
                for (int i = 0; i < 6; i++) {
                    int e = tid + i * 256;
                    int g = e >> 9, rest = e & 511;
                    int n = rest >> 4, kk = rest & 15;
                    Bs[g][n][kk] = Whh[(size_t)(g * 512 + j0 + n) * 512 + k0 + kk];
                }
                __syncthreads();
#pragma unroll
                for (int kk = 0; kk < 16; kk++) {
                    float b0 = Bs[0][tx][kk], b1 = Bs[1][tx][kk], b2 = Bs[2][tx][kk];
#pragma unroll
                    for (int r = 0; r < 4; r++) {
                        float a = As[ty * 4 + r][kk];
                        acc[0][r] = fmaf(a, b0, acc[0][r]);
                        acc[1][r] = fmaf(a, b1, acc[1][r]);
                        acc[2][r] = fmaf(a, b2, acc[2][r]);
                    }
                }
                __syncthreads();
            }

            const int ts = dir ? (127 - t) : t;
            const float* gi = giB + (size_t)ts * 32 * 1536;
            const float b_r = bhh[j], b_z = bhh[512 + j], b_n = bhh[1024 + j];
#pragma unroll
            for (int r = 0; r < 4; r++) {
                int m = ty * 4 + r;
                float ir = gi[m * 1536 + j], iz = gi[m * 1536 + 512 + j], in = gi[m * 1536 + 1024 + j];
                float rr = 1.f / (1.f + expf(-(ir + acc[0][r] + b_r)));
                float zz = 1.f / (1.f + expf(-(iz + acc[1][r] + b_z)));
                float nn = tanhf(in + rr * (acc[2][r] + b_n));
                float hv = (1.f - zz) * nn + zz * hin[m * 512 + j];
                hout[m * 512 + j] = hv;
                encout[((size_t)m * 128 + ts) * 1024 + dir * 512 + j] = hv;
            }
            __syncthreads();
        }
        grid_barrier();
    }

    for (int i = bid * 256 + tid; i < 32 * 1024; i += NB * 256) {
        int b = i >> 10, jj = i & 1023;
        comb[i] = (jj < 512) ? hbuf[b * 512 + jj] : hbuf[16384 + b * 512 + (jj - 512)];
    }
}

// ---------------- persistent decoder with overlapped windows -----------------
__global__ __launch_bounds__(256) void decoder_loop_k(
    float* __restrict__ S,
    const float* __restrict__ emb, const float* __restrict__ attn_Wd,
    const float* __restrict__ attn_v,
    const float* __restrict__ Wih0, const float* __restrict__ Whh0,
    const float* __restrict__ bih0, const float* __restrict__ bhh0,
    const float* __restrict__ Wih1, const float* __restrict__ Whh1,
    const float* __restrict__ bih1, const float* __restrict__ bhh1,
    const float* __restrict__ projW, const float* __restrict__ projb,
    const float* __restrict__ bridgeW, const float* __restrict__ bridgeb,
    float* __restrict__ out)
{
    __shared__ float As16[16][65];
    __shared__ float Bs16[16][65];
    __shared__ float As32[32][17];
    __shared__ float Bs64[64][17];
    __shared__ float sacc[32][65];
    __shared__ float s_h[512];
    __shared__ float s_dq[512];
    __shared__ float s_sc[128];
    __shared__ float s_red[256];
    __shared__ float sv[256];
    __shared__ int   si[256];

    const int tid = threadIdx.x;
    const int bid = blockIdx.x;
    const int NB  = gridDim.x;
    const int lane = tid & 31, warp = tid >> 5;
    const int tx = tid & 15, ty = tid >> 4;
    const int mmq = tid >> 2;           // 0..63  (pipelined loader row)
    const int kq  = (tid & 3) * 4;      // 0,4,8,12 (pipelined loader k-quad)

    const float* encout  = S + OFF_ENCOUT;
    const float* encproj = S + OFF_ENCPROJ;
    const float* comb    = S + OFF_COMB;
    float* bridge = S + OFF_BRIDGE;
    float* h0buf  = S + OFF_H0BUF;
    float* h1buf  = S + OFF_H1BUF;
    float* ctx    = S + OFF_CTX;
    float* logits = S + OFF_LOGITS;
    float* gbuf   = S + OFF_GBUF;
    float* gbuf1  = S + OFF_GBUF1;
    int*   tok    = (int*)(S + OFF_TOK);

    // ---- prologue ----
    for (int i = bid * 256 + tid; i < 32 * 1024; i += NB * 256) {
        int b = i >> 10, n = i & 1023;
        const float* a = comb + b * 1024;
        const float* w = bridgeW + (size_t)n * 1024;
        float s = bridgeb[n];
        for (int k = 0; k < 1024; k++) s = fmaf(a[k], w[k], s);
        bridge[i] = s;
    }
    grid_barrier();
    for (int i = bid * 256 + tid; i < 32 * 1024; i += NB * 256) {
        int b = i >> 10, j = i & 1023;
        float v = bridge[i];
        if (j < 512) h0buf[b * 512 + j] = v; else h1buf[b * 512 + (j - 512)] = v;
    }
    if (bid == 0 && tid < 32) { tok[tid] = 1; out[tid * MAXDEC] = 1.0f; }
    grid_barrier();

    for (int s = 0; s < NSTEPS; s++) {
        const int p = s & 1, q = 1 - p;
        const float* h0in = h0buf + p * 16384;
        float*       h0out = h0buf + q * 16384;
        const float* h1in = h1buf + p * 16384;
        float*       h1out = h1buf + q * 16384;

        // ==== W1: attention (0..31) || gates0 partial emb+h0 (32..63)
        //          || gates1 h-part (64..95)
        for (int job = bid; job < 96; job += NB) {
            if (job < 32) {
                int b = job;
                for (int i = tid; i < 512; i += 256) s_h[i] = h1in[b * 512 + i];
                __syncthreads();
                for (int a = warp; a < 512; a += 8) {
                    const float* wr = attn_Wd + (size_t)a * 512;
                    float acc = 0.f;
                    for (int k = lane; k < 512; k += 32) acc = fmaf(s_h[k], wr[k], acc);
#pragma unroll
                    for (int o = 16; o; o >>= 1) acc += __shfl_xor_sync(0xffffffffu, acc, o);
                    if (lane == 0) s_dq[a] = acc;
                }
                __syncthreads();
                for (int t = warp; t < 128; t += 8) {
                    const float* ep = encproj + ((size_t)b * 128 + t) * 512;
                    float acc = 0.f;
                    for (int a = lane; a < 512; a += 32)
                        acc = fmaf(tanhf(ep[a] + s_dq[a]), attn_v[a], acc);
#pragma unroll
                    for (int o = 16; o; o >>= 1) acc += __shfl_xor_sync(0xffffffffu, acc, o);
                    if (lane == 0) s_sc[t] = acc;
                }
                __syncthreads();
                float mv = (tid < 128) ? s_sc[tid] : -INFINITY;
                s_red[tid] = mv; __syncthreads();
                for (int o = 128; o; o >>= 1) {
                    if (tid < o) s_red[tid] = fmaxf(s_red[tid], s_red[tid + o]);
                    __syncthreads();
                }
                float mx = s_red[0]; __syncthreads();
                float ev = (tid < 128) ? expf(s_sc[tid] - mx) : 0.f;
                s_red[tid] = ev; __syncthreads();
                for (int o = 128; o; o >>= 1) {
                    if (tid < o) s_red[tid] += s_red[tid + o];
                    __syncthreads();
                }
                float dn = s_red[0]; __syncthreads();
                if (tid < 128) s_sc[tid] = ev / dn;
                __syncthreads();
                for (int j = tid; j < 1024; j += 256) {
                    const float* eo = encout + (size_t)b * 131072 + j;
                    float acc = 0.f;
#pragma unroll 4
                    for (int t = 0; t < 128; t++) acc = fmaf(s_sc[t], eo[(size_t)t * 1024], acc);
                    ctx[b * 1024 + j] = acc;
                }
                __syncthreads();
            } else if (job < 64) {
                // gates0 partial: K over {emb 0..511, h0 1536..2047}
                const int jobx = job - 32;
                const int j0 = jobx * 16;
                float acc[2][4] = {{0,0,0,0},{0,0,0,0}};
                for (int kb = 0; kb < 1024; kb += 16) {
                    const int k0 = (kb < 512) ? kb : (kb + 1024);
#pragma unroll
                    for (int rep = 0; rep < 2; rep++) {
                        int e = tid + rep * 256;
                        int m = e >> 4, kk = e & 15;
                        int k = k0 + kk;
                        float av;
                        if (k < 512) {
                            int tk = tok[m];
                            if (tk < 0) tk = 0;
                            if (tk >= VOCAB) tk = VOCAB - 1;
                            av = emb[(size_t)tk * 512 + k];
                        } else av = h0in[m * 512 + (k - 1536)];
                        As32[m][kk] = av;
                    }
#pragma unroll
                    for (int i = 0; i < 4; i++) {
                        int e = tid + i * 256;
                        int c = e >> 4, kk = e & 15;
                        int k = k0 + kk;
                        int g = c >> 4, jj = c & 15;
                        float bv;
                        if (g < 2) {
                            int row = g * 512 + j0 + jj;
                            bv = (k < 1536) ? Wih0[(size_t)row * 1536 + k]
                                            : Whh0[(size_t)row * 512 + (k - 1536)];
                        } else if (g == 2) {
                            int row = 1024 + j0 + jj;
                            bv = (k < 1536) ? Wih0[(size_t)row * 1536 + k] : 0.f;
                        } else {
                            int row = 1024 + j0 + jj;
                            bv = (k >= 1536) ? Whh0[(size_t)row * 512 + (k - 1536)] : 0.f;
                        }
                        Bs64[c][kk] = bv;
                    }
                    __syncthreads();
#pragma unroll
                    for (int kk = 0; kk < 16; kk++) {
                        float a0 = As32[ty * 2][kk], a1 = As32[ty * 2 + 1][kk];
#pragma unroll
                        for (int cc = 0; cc < 4; cc++) {
                            float bv = Bs64[tx + 16 * cc][kk];
                            acc[0][cc] = fmaf(a0, bv, acc[0][cc]);
                            acc[1][cc] = fmaf(a1, bv, acc[1][cc]);
                        }
                    }
                    __syncthreads();
                }
#pragma unroll
                for (int rep = 0; rep < 2; rep++)
#pragma unroll
                    for (int cc = 0; cc < 4; cc++)
                        gbuf[(ty * 2 + rep) * 2048 + jobx * 64 + tx + 16 * cc] = acc[rep][cc];
                __syncthreads();
            } else {
                // gates1 h-part: K=512 over h1in
                const int jobx = job - 64;
                const int j0 = jobx * 16;
                float acc[2][4] = {{0,0,0,0},{0,0,0,0}};
                for (int k0 = 0; k0 < 512; k0 += 16) {
#pragma unroll
                    for (int rep = 0; rep < 2; rep++) {
                        int e = tid + rep * 256;
                        int m = e >> 4, kk = e & 15;
                        As32[m][kk] = h1in[m * 512 + k0 + kk];
                    }
#pragma unroll
                    for (int i = 0; i < 4; i++) {
                        int e = tid + i * 256;
                        int c = e >> 4, kk = e & 15;
                        int k = k0 + kk;
                        int g = c >> 4, jj = c & 15;
                        float bv;
                        if (g < 2) {
                            int row = g * 512 + j0 + jj;
                            bv = Whh1[(size_t)row * 512 + k];
                        } else if (g == 3) {
                            int row = 1024 + j0 + jj;
                            bv = Whh1[(size_t)row * 512 + k];
                        } else bv = 0.f;
                        Bs64[c][kk] = bv;
                    }
                    __syncthreads();
#pragma unroll
                    for (int kk = 0; kk < 16; kk++) {
                        float a0 = As32[ty * 2][kk], a1 = As32[ty * 2 + 1][kk];
#pragma unroll
                        for (int cc = 0; cc < 4; cc++) {
                            float bv = Bs64[tx + 16 * cc][kk];
                            acc[0][cc] = fmaf(a0, bv, acc[0][cc]);
                            acc[1][cc] = fmaf(a1, bv, acc[1][cc]);
                        }
                    }
                    __syncthreads();
                }
#pragma unroll
                for (int rep = 0; rep < 2; rep++)
#pragma unroll
                    for (int cc = 0; cc < 4; cc++)
                        gbuf1[(ty * 2 + rep) * 2048 + jobx * 64 + tx + 16 * cc] = acc[rep][cc];
                __syncthreads();
            }
        }
        grid_barrier();

        // ==== W2: gates0 finalize (ctx K, 0..31) || logits-ctx pipelined (32..156)
        for (int job = bid; job < 157; job += NB) {
            if (job < 32) {
                const int j0 = job * 16;
                float acc[2][4];
#pragma unroll
                for (int rep = 0; rep < 2; rep++)
#pragma unroll
                    for (int cc = 0; cc < 4; cc++)
                        acc[rep][cc] = gbuf[(ty * 2 + rep) * 2048 + job * 64 + tx + 16 * cc];
                for (int k0 = 512; k0 < 1536; k0 += 16) {
#pragma unroll
                    for (int rep = 0; rep < 2; rep++) {
                        int e = tid + rep * 256;
                        int m = e >> 4, kk = e & 15;
                        As32[m][kk] = ctx[m * 1024 + (k0 + kk - 512)];
                    }
#pragma unroll
                    for (int i = 0; i < 4; i++) {
                        int e = tid + i * 256;
                        int c = e >> 4, kk = e & 15;
                        int k = k0 + kk;
                        int g = c >> 4, jj = c & 15;
                        float bv;
                        if (g < 2) {
                            int row = g * 512 + j0 + jj;
                            bv = Wih0[(size_t)row * 1536 + k];
                        } else if (g == 2) {
                            int row = 1024 + j0 + jj;
                            bv = Wih0[(size_t)row * 1536 + k];
                        } else bv = 0.f;
                        Bs64[c][kk] = bv;
                    }
                    __syncthreads();
#pragma unroll
                    for (int kk = 0; kk < 16; kk++) {
                        float a0 = As32[ty * 2][kk], a1 = As32[ty * 2 + 1][kk];
#pragma unroll
                        for (int cc = 0; cc < 4; cc++) {
                            float bv = Bs64[tx + 16 * cc][kk];
                            acc[0][cc] = fmaf(a0, bv, acc[0][cc]);
                            acc[1][cc] = fmaf(a1, bv, acc[1][cc]);
                        }
                    }
                    __syncthreads();
                }
#pragma unroll
                for (int rep = 0; rep < 2; rep++)
#pragma unroll
                    for (int cc = 0; cc < 4; cc++)
                        sacc[ty * 2 + rep][tx + 16 * cc] = acc[rep][cc];
                __syncthreads();
                for (int i = tid; i < 512; i += 256) {
                    int b = i >> 4, jj = i & 15;
                    int j = j0 + jj;
                    float r_  = sacc[b][jj]      + bih0[j]        + bhh0[j];
                    float z_  = sacc[b][16 + jj] + bih0[512 + j]  + bhh0[512 + j];
                    float in_ = sacc[b][32 + jj] + bih0[1024 + j];
                    float hn_ = sacc[b][48 + jj] + bhh0[1024 + j];
                    float rr = 1.f / (1.f + expf(-r_));
                    float zz = 1.f / (1.f + expf(-z_));
                    float nn = tanhf(in_ + rr * hn_);
                    h0out[b * 512 + j] = (1.f - zz) * nn + zz * h0in[b * 512 + j];
                }
                __syncthreads();
            } else {
                // logits-ctx: pipelined float4, K in [512,1536)
                const int n0 = (job - 32) * 64;
                float4 ra, rb;
                rb = *(const float4*)(projW + (size_t)(n0 + mmq) * 1536 + 512 + kq);
                if (mmq < 32) ra = *(const float4*)(ctx + mmq * 1024 + kq);
                else ra = make_float4(0.f, 0.f, 0.f, 0.f);
                float acc[2][4] = {{0,0,0,0},{0,0,0,0}};
                for (int k0 = 512; k0 < 1536; k0 += 16) {
                    As16[kq + 0][mmq] = ra.x; As16[kq + 1][mmq] = ra.y;
                    As16[kq + 2][mmq] = ra.z; As16[kq + 3][mmq] = ra.w;
                    Bs16[kq + 0][mmq] = rb.x; Bs16[kq + 1][mmq] = rb.y;
                    Bs16[kq + 2][mmq] = rb.z; Bs16[kq + 3][mmq] = rb.w;
                    __syncthreads();
                    int kn = k0 + 16;
                    if (kn < 1536) {
                        rb = *(const float4*)(projW + (size_t)(n0 + mmq) * 1536 + kn + kq);
                        if (mmq < 32) ra = *(const float4*)(ctx + mmq * 1024 + (kn - 512) + kq);
                    }
#pragma unroll
                    for (int kk = 0; kk < 16; kk++) {
                        float a0 = As16[kk][ty], a1 = As16[kk][ty + 16];
#pragma unroll
                        for (int j = 0; j < 4; j++) {
                            float bv = Bs16[kk][tx + 16 * j];
                            acc[0][j] = fmaf(a0, bv, acc[0][j]);
                            acc[1][j] = fmaf(a1, bv, acc[1][j]);
                        }
                    }
                    __syncthreads();
                }
#pragma unroll
                for (int i = 0; i < 2; i++) {
                    int m = ty + 16 * i;
#pragma unroll
                    for (int j = 0; j < 4; j++) {
                        int n = n0 + tx + 16 * j;
                        logits[(size_t)m * VOCAB + n] = acc[i][j] + projb[n];
                    }
                }
                __syncthreads();
            }
        }
        grid_barrier();

        // ==== W3: gates1 finalize — x-part only (K=512 over h0out), 32 jobs
        for (int job = bid; job < 32; job += NB) {
            const int j0 = job * 16;
            float acc[2][4];
#pragma unroll
            for (int rep = 0; rep < 2; rep++)
#pragma unroll
                for (int cc = 0; cc < 4; cc++)
                    acc[rep][cc] = gbuf1[(ty * 2 + rep) * 2048 + job * 64 + tx + 16 * cc];
            for (int k0 = 0; k0 < 512; k0 += 16) {
#pragma unroll
                for (int rep = 0; rep < 2; rep++) {
                    int e = tid + rep * 256;
                    int m = e >> 4, kk = e & 15;
                    As32[m][kk] = h0out[m * 512 + k0 + kk];
                }
#pragma unroll
                for (int i = 0; i < 4; i++) {
                    int e = tid + i * 256;
                    int c = e >> 4, kk = e & 15;
                    int k = k0 + kk;
                    int g = c >> 4, jj = c & 15;
                    float bv;
                    if (g < 2) {
                        int row = g * 512 + j0 + jj;
                        bv = Wih1[(size_t)row * 512 + k];
                    } else if (g == 2) {
                        int row = 1024 + j0 + jj;
                        bv = Wih1[(size_t)row * 512 + k];
                    } else bv = 0.f;
                    Bs64[c][kk] = bv;
                }
                __syncthreads();
#pragma unroll
                for (int kk = 0; kk < 16; kk++) {
                    float a0 = As32[ty * 2][kk], a1 = As32[ty * 2 + 1][kk];
#pragma unroll
                    for (int cc = 0; cc < 4; cc++) {
                        float bv = Bs64[tx + 16 * cc][kk];
                        acc[0][cc] = fmaf(a0, bv, acc[0][cc]);
                        acc[1][cc] = fmaf(a1, bv, acc[1][cc]);
                    }
                }
                __syncthreads();
            }
#pragma unroll
            for (int rep = 0; rep < 2; rep++)
#pragma unroll
                for (int cc = 0; cc < 4; cc++)
                    sacc[ty * 2 + rep][tx + 16 * cc] = acc[rep][cc];
            __syncthreads();
            for (int i = tid; i < 512; i += 256) {
                int b = i >> 4, jj = i & 15;
                int j = j0 + jj;
                float r_  = sacc[b][jj]      + bih1[j]        + bhh1[j];
                float z_  = sacc[b][16 + jj] + bih1[512 + j]  + bhh1[512 + j];
                float in_ = sacc[b][32 + jj] + bih1[1024 + j];
                float hn_ = sacc[b][48 + jj] + bhh1[1024 + j];
                float rr = 1.f / (1.f + expf(-r_));
                float zz = 1.f / (1.f + expf(-z_));
                float nn = tanhf(in_ + rr * hn_);
                h1out[b * 512 + j] = (1.f - zz) * nn + zz * h1in[b * 512 + j];
            }
            __syncthreads();
        }
        grid_barrier();

        // ==== W4: logits += h1 part (K=512), pipelined float4, 125 jobs
        for (int job = bid; job < 125; job += NB) {
            const int n0 = job * 64;
            float4 ra, rb;
            rb = *(const float4*)(projW + (size_t)(n0 + mmq) * 1536 + kq);
            if (mmq < 32) ra = *(const float4*)(h1out + mmq * 512 + kq);
            else ra = make_float4(0.f, 0.f, 0.f, 0.f);
            float acc[2][4] = {{0,0,0,0},{0,0,0,0}};
            for (int k0 = 0; k0 < 512; k0 += 16) {
                As16[kq + 0][mmq] = ra.x; As16[kq + 1][mmq] = ra.y;
                As16[kq + 2][mmq] = ra.z; As16[kq + 3][mmq] = ra.w;
                Bs16[kq + 0][mmq] = rb.x; Bs16[kq + 1][mmq] = rb.y;
                Bs16[kq + 2][mmq] = rb.z; Bs16[kq + 3][mmq] = rb.w;
                __syncthreads();
                int kn = k0 + 16;
                if (kn < 512) {
                    rb = *(const float4*)(projW + (size_t)(n0 + mmq) * 1536 + kn + kq);
                    if (mmq < 32) ra = *(const float4*)(h1out + mmq * 512 + kn + kq);
                }
#pragma unroll
                for (int kk = 0; kk < 16; kk++) {
                    float a0 = As16[kk][ty], a1 = As16[kk][ty + 16];
#pragma unroll
                    for (int j = 0; j < 4; j++) {
                        float bv = Bs16[kk][tx + 16 * j];
                        acc[0][j] = fmaf(a0, bv, acc[0][j]);
                        acc[1][j] = fmaf(a1, bv, acc[1][j]);
                    }
                }
                __syncthreads();
            }
#pragma unroll
            for (int i = 0; i < 2; i++) {
                int m = ty + 16 * i;
#pragma unroll
                for (int j = 0; j < 4; j++) {
                    int n = n0 + tx + 16 * j;
                    logits[(size_t)m * VOCAB + n] += acc[i][j];
                }
            }
            __syncthreads();
        }
        grid_barrier();

        // ==== W5: argmax, 32 jobs
        for (int b = bid; b < 32; b += NB) {
            float best = -INFINITY; int bi = SENTINEL;
            for (int i = tid; i < VOCAB; i += 256) {
                float v = logits[(size_t)b * VOCAB + i];
                if (v > best) { best = v; bi = i; }
            }
            sv[tid] = best; si[tid] = bi; __syncthreads();
            for (int o = 128; o; o >>= 1) {
                if (tid < o) {
                    if (sv[tid + o] > sv[tid] ||
                        (sv[tid + o] == sv[tid] && si[tid + o] < si[tid])) {
                        sv[tid] = sv[tid + o]; si[tid] = si[tid + o];
                    }
                }
                __syncthreads();
            }
            if (tid == 0) { tok[b] = si[0]; out[b * MAXDEC + s + 1] = (float)si[0]; }
            __syncthreads();
        }
        grid_barrier();
    }
}

// ---------------- host ----------------
static inline unsigned cdiv(unsigned a, unsigned b) { return (a + b - 1) / b; }

static void gemm(const float* A, const float* Bm, const float* bias, float* C,
                 int M, int N, int K, int relu)
{
    dim3 grid(cdiv(M, 64), cdiv(N, 64));
    gemm_abt<<<grid, 256>>>(A, Bm, bias, C, M, N, K, relu);
}

enum {
    I_FEAT, I_CW1, I_CB1, I_CW2, I_CB2,
    I_EWIHF, I_EWHHF, I_EBIHF, I_EBHHF,
    I_EWIHB, I_EWHHB, I_EBIHB, I_EBHHB,
    I_BRW, I_BRB, I_EMB, I_AWE, I_AWD, I_AV,
    I_DWIH0, I_DWHH0, I_DBIH0, I_DBHH0,
    I_DWIH1, I_DWHH1, I_DBIH1, I_DBHH1,
    I_PW, I_PB, N_LOGICAL
};

extern "C" void kernel_launch(void* const* d_in, const int* in_sizes, int n_in,
                              void* d_out, int out_size)
{
    (void)out_size;
    static const int posA[N_LOGICAL] = {
        0, 1, 2, 3, 4,  5, 6, 7, 8,  9, 10, 11, 12,
        13, 14, 15, 16, 17, 18,  19, 20, 21, 22,  23, 24, 25, 26,  27, 28 };
    static const int posB[N_LOGICAL] = {
        26, 7, 5, 8, 6,  21, 19, 25, 23,  20, 18, 24, 22,
        3, 4, 17, 1, 0, 2,  11, 9, 15, 13,  12, 10, 16, 14,  27, 28 };
    static const long long esz[N_LOGICAL] = {
        4194304, 655360, 512, 1310720, 512,
        786432, 786432, 1536, 1536,  786432, 786432, 1536, 1536,
        1048576, 1024, 4096000, 524288, 262144, 512,
        2359296, 786432, 1536, 1536,  786432, 786432, 1536, 1536,
        12288000, 8000 };

    const int* pos = posA;
    if (n_in >= N_LOGICAL && in_sizes) {
        int misB = 0;
        for (int i = 0; i < N_LOGICAL; i++)
            if ((long long)in_sizes[posB[i]] != esz[i]) misB++;
        if (misB == 0) {
            int misA = 0;
            for (int i = 0; i < N_LOGICAL; i++)
                if ((long long)in_sizes[posA[i]] != esz[i]) misA++;
            if (misA > 0) pos = posB;
        }
    }

    const float* features = (const float*)d_in[pos[I_FEAT]];
    const float* conv_w1  = (const float*)d_in[pos[I_CW1]];
    const float* conv_b1  = (const float*)d_in[pos[I_CB1]];
    const float* conv_w2  = (const float*)d_in[pos[I_CW2]];
    const float* conv_b2  = (const float*)d_in[pos[I_CB2]];
    const float* Wih_f    = (const float*)d_in[pos[I_EWIHF]];
    const float* Whh_f    = (const float*)d_in[pos[I_EWHHF]];
    const float* bih_f    = (const float*)d_in[pos[I_EBIHF]];
    const float* bhh_f    = (const float*)d_in[pos[I_EBHHF]];
    const float* Wih_b    = (const float*)d_in[pos[I_EWIHB]];
    const float* Whh_b    = (const float*)d_in[pos[I_EWHHB]];
    const float* bih_b    = (const float*)d_in[pos[I_EBIHB]];
    const float* bhh_b    = (const float*)d_in[pos[I_EBHHB]];
    const float* bridge_W = (const float*)d_in[pos[I_BRW]];
    const float* bridge_b = (const float*)d_in[pos[I_BRB]];
    const float* emb      = (const float*)d_in[pos[I_EMB]];
    const float* attn_We  = (const float*)d_in[pos[I_AWE]];
    const float* attn_Wd  = (const float*)d_in[pos[I_AWD]];
    const float* attn_v   = (const float*)d_in[pos[I_AV]];
    const float* dWih0    = (const float*)d_in[pos[I_DWIH0]];
    const float* dWhh0    = (const float*)d_in[pos[I_DWHH0]];
    const float* dbih0    = (const float*)d_in[pos[I_DBIH0]];
    const float* dbhh0    = (const float*)d_in[pos[I_DBHH0]];
    const float* dWih1    = (const float*)d_in[pos[I_DWIH1]];
    const float* dWhh1    = (const float*)d_in[pos[I_DWHH1]];
    const float* dbih1    = (const float*)d_in[pos[I_DBIH1]];
    const float* dbhh1    = (const float*)d_in[pos[I_DBHH1]];
    const float* proj_W   = (const float*)d_in[pos[I_PW]];
    const float* proj_b   = (const float*)d_in[pos[I_PB]];
    float* out = (float*)d_out;

    float* S = nullptr;
    cudaGetSymbolAddress((void**)&S, g_scratch);

    float* patch   = S + OFF_PATCH;
    float* c1      = S + OFF_C1;
    float* c2      = S + OFF_C2;
    float* xtbc    = S + OFF_XTBC;
    float* gif     = S + OFF_GIF;
    float* gib     = S + OFF_GIB;
    float* encout  = S + OFF_ENCOUT;
    float* encproj = S + OFF_ENCPROJ;
    float* hbuf    = S + OFF_HBUF;
    float* comb    = S + OFF_COMB;

    int dev = 0; cudaGetDevice(&dev);
    int nsm = 0; cudaDeviceGetAttribute(&nsm, cudaDevAttrMultiProcessorCount, dev);
    if (nsm <= 0) nsm = 1;
    int occE = 0, occD = 0;
    cudaOccupancyMaxActiveBlocksPerMultiprocessor(&occE, encoder_loop_k, 256, 0);
    cudaOccupancyMaxActiveBlocksPerMultiprocessor(&occD, decoder_loop_k, 256, 0);
    if (occE < 1) occE = 1;
    if (occD < 1) occD = 1;
    long long ecap = (long long)nsm * occE;
    long long dcap = (long long)nsm * occD;
    int enc_blk = (int)(ecap < 32  ? ecap : 32);
    int dec_blk = (int)(dcap < 157 ? dcap : 157);

    im2col1<<<cdiv(8192u * 1280u, 256u), 256>>>(features, patch);
    gemm(patch, conv_w1, conv_b1, c1, 8192, 512, 1280, 1);
    im2col2<<<cdiv(4096u * 2560u, 256u), 256>>>(c1, patch);
    gemm(patch, conv_w2, conv_b2, c2, 4096, 512, 2560, 1);
    xpose_bt<<<cdiv(4096u * 512u, 256u), 256>>>(c2, xtbc);

    gemm(xtbc, Wih_f, bih_f, gif, 4096, 1536, 512, 0);
    gemm(xtbc, Wih_b, bih_b, gib, 4096, 1536, 512, 0);

    encoder_loop_k<<<enc_blk, 256>>>(gif, gib, Whh_f, Whh_b, bhh_f, bhh_b,
                                     encout, comb, hbuf);

    gemm(encout, attn_We, nullptr, encproj, 4096, 512, 1024, 0);

    decoder_loop_k<<<dec_blk, 256>>>(S, emb, attn_Wd, attn_v,
                                     dWih0, dWhh0, dbih0, dbhh0,
                                     dWih1, dWhh1, dbih1, dbhh1,
                                     proj_W, proj_b, bridge_W, bridge_b, out);
}

// round 17
// speedup vs baseline: 2.1949x; 1.0645x over previous
#include <cuda_runtime.h>
#include <math.h>

#define VOCAB  8000
#define MAXDEC 50
#define NSTEPS 49
#define SENTINEL 7777

// ---------------- scratch layout (floats) ----------------
#define OFF_PATCH    0ull
#define OFF_C1       10485760ull
#define OFF_C2       14680064ull
#define OFF_XTBC     16777216ull
#define OFF_GIF      18874368ull
#define OFF_GIB      25165824ull
#define OFF_ENCOUT   31457280ull
#define OFF_ENCPROJ  35651584ull
#define OFF_HBUF     37748736ull
#define OFF_COMB     37814272ull
#define OFF_BRIDGE   37847040ull
#define OFF_H0BUF    37879808ull
#define OFF_H1BUF    37912576ull
#define OFF_CTX      37945344ull
#define OFF_LOGITS   37978112ull
#define OFF_GBUF     38234112ull
#define OFF_GBUF1    38299648ull
#define OFF_TOK      38365184ull
#define SCRATCH_FLOATS 38365248ull

static __device__ float g_scratch[SCRATCH_FLOATS];

// ---------------- software grid barrier ----------------
__device__ unsigned g_bar_cnt = 0;
__device__ unsigned g_bar_gen = 0;

__device__ __forceinline__ void grid_barrier()
{
    unsigned nblk = gridDim.x;
    __threadfence();
    __syncthreads();
    if (threadIdx.x == 0) {
        unsigned gen = *(volatile unsigned*)&g_bar_gen;
        if (atomicAdd(&g_bar_cnt, 1u) == nblk - 1u) {
            atomicExch(&g_bar_cnt, 0u);
            __threadfence();
            *(volatile unsigned*)&g_bar_gen = gen + 1u;
        } else {
            while (*(volatile unsigned*)&g_bar_gen == gen) __nanosleep(32);
        }
    }
    __syncthreads();
    __threadfence();
}

// ---------------- standalone GEMM (strided conflict-free tile) ---------------
__global__ void gemm_abt(const float* __restrict__ A, const float* __restrict__ Bm,
                         const float* __restrict__ bias, float* __restrict__ C,
                         int M, int N, int K, int relu)
{
    __shared__ float As[16][65];
    __shared__ float Bs[16][65];
    int tid = threadIdx.x;
    int tx = tid & 15, ty = tid >> 4;
    int m0 = blockIdx.x * 64, n0 = blockIdx.y * 64;
    float acc[4][4];
#pragma unroll
    for (int i = 0; i < 4; i++)
#pragma unroll
        for (int j = 0; j < 4; j++) acc[i][j] = 0.f;

    for (int k0 = 0; k0 < K; k0 += 16) {
#pragma unroll
        for (int r = 0; r < 4; r++) {
            int i  = tid + r * 256;
            int mm = i >> 4, kk = i & 15;
            As[kk][mm] = (m0 + mm < M) ? A[(size_t)(m0 + mm) * K + k0 + kk] : 0.f;
            Bs[kk][mm] = (n0 + mm < N) ? Bm[(size_t)(n0 + mm) * K + k0 + kk] : 0.f;
        }
        __syncthreads();
#pragma unroll
        for (int kk = 0; kk < 16; kk++) {
            float a[4], b[4];
#pragma unroll
            for (int i = 0; i < 4; i++) a[i] = As[kk][ty + 16 * i];
#pragma unroll
            for (int j = 0; j < 4; j++) b[j] = Bs[kk][tx + 16 * j];
#pragma unroll
            for (int i = 0; i < 4; i++)
#pragma unroll
                for (int j = 0; j < 4; j++) acc[i][j] = fmaf(a[i], b[j], acc[i][j]);
        }
        __syncthreads();
    }
#pragma unroll
    for (int i = 0; i < 4; i++) {
        int m = m0 + ty + 16 * i;
        if (m >= M) continue;
#pragma unroll
        for (int j = 0; j < 4; j++) {
            int n = n0 + tx + 16 * j;
            if (n >= N) continue;
            float v = acc[i][j] + (bias ? bias[n] : 0.f);
            if (relu) v = fmaxf(v, 0.f);
            C[(size_t)m * N + n] = v;
        }
    }
}

// ---------------- conv im2col / transpose ----------------
__global__ void im2col1(const float* __restrict__ f, float* __restrict__ patch)
{
    long long idx = (long long)blockIdx.x * 256 + threadIdx.x;
    if (idx >= 8192LL * 1280) return;
    int col = (int)(idx % 1280);
    int row = (int)(idx / 1280);
    int ol = row & 255, b = row >> 8;
    int ic = col / 5, kk = col % 5;
    int l = 2 * ol - 2 + kk;
    patch[idx] = (l >= 0 && l < 512) ? f[((size_t)b * 512 + l) * 256 + ic] : 0.f;
}

__global__ void im2col2(const float* __restrict__ c1, float* __restrict__ patch)
{
    long long idx = (long long)blockIdx.x * 256 + threadIdx.x;
    if (idx >= 4096LL * 2560) return;
    int col = (int)(idx % 2560);
    int row = (int)(idx / 2560);
    int ol = row & 127, b = row >> 7;
    int ic = col / 5, kk = col % 5;
    int l = 2 * ol - 2 + kk;
    patch[idx] = (l >= 0 && l < 256) ? c1[((size_t)b * 256 + l) * 512 + ic] : 0.f;
}

__global__ void xpose_bt(const float* __restrict__ c2, float* __restrict__ xtbc)
{
    int idx = blockIdx.x * 256 + threadIdx.x;
    if (idx >= 4096 * 512) return;
    int c = idx & 511;
    int row = idx >> 9;
    int t = row >> 5, b = row & 31;
    xtbc[idx] = c2[((size_t)b * 128 + t) * 512 + c];
}

// ---------------- persistent encoder (validated body) ------------------------
__global__ __launch_bounds__(256) void encoder_loop_k(
    const float* __restrict__ gif, const float* __restrict__ gib,
    const float* __restrict__ WhhF, const float* __restrict__ WhhB,
    const float* __restrict__ bhhF, const float* __restrict__ bhhB,
    float* __restrict__ encout, float* __restrict__ comb, float* __restrict__ hbuf)
{
    __shared__ float As[32][17];
    __shared__ float Bs[3][32][17];
    const int tid = threadIdx.x;
    const int bid = blockIdx.x;
    const int NB  = gridDim.x;

    for (int i = bid * 256 + tid; i < 32768; i += NB * 256) hbuf[i] = 0.f;
    grid_barrier();

    for (int t = 0; t < 128; t++) {
        for (int job = bid; job < 32; job += NB) {
            const int dir = job >> 4;
            const int j0  = (job & 15) * 32;
            const float* Whh = dir ? WhhB : WhhF;
            const float* bhh = dir ? bhhB : bhhF;
            const float* giB = dir ? gib : gif;
            const int tx = tid & 31;
            const int ty = tid >> 5;
            const int j  = j0 + tx;

            const float* hin  = hbuf + (t & 1) * 32768 + dir * 16384;
            float*       hout = hbuf + ((t + 1) & 1) * 32768 + dir * 16384;

            float acc[3][4] = {{0,0,0,0},{0,0,0,0},{0,0,0,0}};

            for (int k0 = 0; k0 < 512; k0 += 16) {
                {
                    int m = tid >> 4, kk = tid & 15;
                    As[m][kk] = hin[m * 512 + k0 + kk];
                    int e = tid + 256; m = e >> 4; kk = e & 15;
                    As[m][kk] = hin[m * 512 + k0 + kk];
                }
#pragma unroll
                for (int i = 0; i < 6; i++) {
                    int e = tid + i * 256;
                    int g = e >> 9, rest = e & 511;
                    int n = rest >> 4, kk = rest & 15;
                    Bs[g][n][kk] = Whh[(size_t)(g * 512 + j0 + n) * 512 + k0 + kk];
                }
                __syncthreads();
#pragma unroll
                for (int kk = 0; kk < 16; kk++) {
                    float b0 = Bs[0][tx][kk], b1 = Bs[1][tx][kk], b2 = Bs[2][tx][kk];
#pragma unroll
                    for (int r = 0; r < 4; r++) {
                        float a = As[ty * 4 + r][kk];
                        acc[0][r] = fmaf(a, b0, acc[0][r]);
                        acc[1][r] = fmaf(a, b1, acc[1][r]);
                        acc[2][r] = fmaf(a, b2, acc[2][r]);
                    }
                }
                __syncthreads();
            }

            const int ts = dir ? (127 - t) : t;
            const float* gi = giB + (size_t)ts * 32 * 1536;
            const float b_r = bhh[j], b_z = bhh[512 + j], b_n = bhh[1024 + j];
#pragma unroll
            for (int r = 0; r < 4; r++) {
                int m = ty * 4 + r;
                float ir = gi[m * 1536 + j], iz = gi[m * 1536 + 512 + j], in = gi[m * 1536 + 1024 + j];
                float rr = 1.f / (1.f + expf(-(ir + acc[0][r] + b_r)));
                float zz = 1.f / (1.f + expf(-(iz + acc[1][r] + b_z)));
                float nn = tanhf(in + rr * (acc[2][r] + b_n));
                float hv = (1.f - zz) * nn + zz * hin[m * 512 + j];
                hout[m * 512 + j] = hv;
                encout[((size_t)m * 128 + ts) * 1024 + dir * 512 + j] = hv;
            }
            __syncthreads();
        }
        grid_barrier();
    }

    for (int i = bid * 256 + tid; i < 32 * 1024; i += NB * 256) {
        int b = i >> 10, jj = i & 1023;
        comb[i] = (jj < 512) ? hbuf[b * 512 + jj] : hbuf[16384 + b * 512 + (jj - 512)];
    }
}

// ---------------- persistent decoder with overlapped, pipelined windows ------
__global__ __launch_bounds__(256) void decoder_loop_k(
    float* __restrict__ S,
    const float* __restrict__ emb, const float* __restrict__ attn_Wd,
    const float* __restrict__ attn_v,
    const float* __restrict__ Wih0, const float* __restrict__ Whh0,
    const float* __restrict__ bih0, const float* __restrict__ bhh0,
    const float* __restrict__ Wih1, const float* __restrict__ Whh1,
    const float* __restrict__ bih1, const float* __restrict__ bhh1,
    const float* __restrict__ projW, const float* __restrict__ projb,
    const float* __restrict__ bridgeW, const float* __restrict__ bridgeb,
    float* __restrict__ out)
{
    __shared__ float As16[16][65];
    __shared__ float Bs16[16][65];
    __shared__ float As32[32][17];
    __shared__ float Bs64[64][17];
    __shared__ float sacc[32][65];
    __shared__ float s_h[512];
    __shared__ float s_dq[512];
    __shared__ float s_sc[128];
    __shared__ float s_red[256];
    __shared__ float sv[256];
    __shared__ int   si[256];

    const int tid = threadIdx.x;
    const int bid = blockIdx.x;
    const int NB  = gridDim.x;
    const int lane = tid & 31, warp = tid >> 5;
    const int tx = tid & 15, ty = tid >> 4;
    const int mmq = tid >> 2;           // 0..63 (loader row)
    const int kq  = (tid & 3) * 4;      // 0,4,8,12 (loader k-quad)
    const int gjj = mmq & 15;           // B-row j within group
    const int gg  = mmq >> 4;           // B group 0..3

    const float* encout  = S + OFF_ENCOUT;
    const float* encproj = S + OFF_ENCPROJ;
    const float* comb    = S + OFF_COMB;
    float* bridge = S + OFF_BRIDGE;
    float* h0buf  = S + OFF_H0BUF;
    float* h1buf  = S + OFF_H1BUF;
    float* ctx    = S + OFF_CTX;
    float* logits = S + OFF_LOGITS;
    float* gbuf   = S + OFF_GBUF;
    float* gbuf1  = S + OFF_GBUF1;
    int*   tok    = (int*)(S + OFF_TOK);

    // ---- prologue ----
    for (int i = bid * 256 + tid; i < 32 * 1024; i += NB * 256) {
        int b = i >> 10, n = i & 1023;
        const float* a = comb + b * 1024;
        const float* w = bridgeW + (size_t)n * 1024;
        float s = bridgeb[n];
        for (int k = 0; k < 1024; k++) s = fmaf(a[k], w[k], s);
        bridge[i] = s;
    }
    grid_barrier();
    for (int i = bid * 256 + tid; i < 32 * 1024; i += NB * 256) {
        int b = i >> 10, j = i & 1023;
        float v = bridge[i];
        if (j < 512) h0buf[b * 512 + j] = v; else h1buf[b * 512 + (j - 512)] = v;
    }
    if (bid == 0 && tid < 32) { tok[tid] = 1; out[tid * MAXDEC] = 1.0f; }
    grid_barrier();

    const float4 f4z = make_float4(0.f, 0.f, 0.f, 0.f);

    for (int s = 0; s < NSTEPS; s++) {
        const int p = s & 1, q = 1 - p;
        const float* h0in = h0buf + p * 16384;
        float*       h0out = h0buf + q * 16384;
        const float* h1in = h1buf + p * 16384;
        float*       h1out = h1buf + q * 16384;

        // ==== W1: attention (0..31) || gates0 partial (32..63) || gates1 h-part (64..95)
        for (int job = bid; job < 96; job += NB) {
            if (job < 32) {
                int b = job;
                for (int i = tid; i < 512; i += 256) s_h[i] = h1in[b * 512 + i];
                __syncthreads();
                for (int a = warp; a < 512; a += 8) {
                    const float* wr = attn_Wd + (size_t)a * 512;
                    float acc = 0.f;
                    for (int k = lane; k < 512; k += 32) acc = fmaf(s_h[k], wr[k], acc);
#pragma unroll
                    for (int o = 16; o; o >>= 1) acc += __shfl_xor_sync(0xffffffffu, acc, o);
                    if (lane == 0) s_dq[a] = acc;
                }
                __syncthreads();
                for (int t = warp; t < 128; t += 8) {
                    const float* ep = encproj + ((size_t)b * 128 + t) * 512;
                    float acc = 0.f;
                    for (int a = lane; a < 512; a += 32)
                        acc = fmaf(tanhf(ep[a] + s_dq[a]), attn_v[a], acc);
#pragma unroll
                    for (int o = 16; o; o >>= 1) acc += __shfl_xor_sync(0xffffffffu, acc, o);
                    if (lane == 0) s_sc[t] = acc;
                }
                __syncthreads();
                float mv = (tid < 128) ? s_sc[tid] : -INFINITY;
                s_red[tid] = mv; __syncthreads();
                for (int o = 128; o; o >>= 1) {
                    if (tid < o) s_red[tid] = fmaxf(s_red[tid], s_red[tid + o]);
                    __syncthreads();
                }
                float mx = s_red[0]; __syncthreads();
                float ev = (tid < 128) ? expf(s_sc[tid] - mx) : 0.f;
                s_red[tid] = ev; __syncthreads();
                for (int o = 128; o; o >>= 1) {
                    if (tid < o) s_red[tid] += s_red[tid + o];
                    __syncthreads();
                }
                float dn = s_red[0]; __syncthreads();
                if (tid < 128) s_sc[tid] = ev / dn;
                __syncthreads();
                for (int j = tid; j < 1024; j += 256) {
                    const float* eo = encout + (size_t)b * 131072 + j;
                    float acc = 0.f;
#pragma unroll 4
                    for (int t = 0; t < 128; t++) acc = fmaf(s_sc[t], eo[(size_t)t * 1024], acc);
                    ctx[b * 1024 + j] = acc;
                }
                __syncthreads();
            } else if (job < 64) {
                // gates0 partial: sections emb(k 0..511 of Wih0) then h0(k 0..511 of Whh0)
                const int jobx = job - 32;
                const int j0 = jobx * 16;
                const float* browx = (gg < 2) ? Wih0 + (size_t)(gg * 512 + j0 + gjj) * 1536
                                  : (gg == 2) ? Wih0 + (size_t)(1024 + j0 + gjj) * 1536
                                  : (const float*)0;
                const float* browh = (gg < 2) ? Whh0 + (size_t)(gg * 512 + j0 + gjj) * 512
                                  : (gg == 3) ? Whh0 + (size_t)(1024 + j0 + gjj) * 512
                                  : (const float*)0;
                const float* arow_emb = (const float*)0;
                const float* arow_h0 = (const float*)0;
                if (mmq < 32) {
                    int tk = tok[mmq];
                    if (tk < 0) tk = 0;
                    if (tk >= VOCAB) tk = VOCAB - 1;
                    arow_emb = emb + (size_t)tk * 512;
                    arow_h0  = h0in + mmq * 512;
                }
                float4 ra = arow_emb ? *(const float4*)(arow_emb + kq) : f4z;
                float4 rb = browx ? *(const float4*)(browx + kq) : f4z;
                float acc[2][4] = {{0,0,0,0},{0,0,0,0}};
                for (int kb = 0; kb < 64; kb++) {
                    if (mmq < 32) {
                        As32[mmq][kq + 0] = ra.x; As32[mmq][kq + 1] = ra.y;
                        As32[mmq][kq + 2] = ra.z; As32[mmq][kq + 3] = ra.w;
                    }
                    Bs64[mmq][kq + 0] = rb.x; Bs64[mmq][kq + 1] = rb.y;
                    Bs64[mmq][kq + 2] = rb.z; Bs64[mmq][kq + 3] = rb.w;
                    __syncthreads();
                    int kn = kb + 1;
                    if (kn < 64) {
                        if (kn < 32) {
                            int kl = kn * 16;
                            ra = arow_emb ? *(const float4*)(arow_emb + kl + kq) : f4z;
                            rb = browx ? *(const float4*)(browx + kl + kq) : f4z;
                        } else {
                            int kl = (kn - 32) * 16;
                            ra = arow_h0 ? *(const float4*)(arow_h0 + kl + kq) : f4z;
                            rb = browh ? *(const float4*)(browh + kl + kq) : f4z;
                        }
                    }
#pragma unroll
                    for (int kk = 0; kk < 16; kk++) {
                        float a0 = As32[ty * 2][kk], a1 = As32[ty * 2 + 1][kk];
#pragma unroll
                        for (int cc = 0; cc < 4; cc++) {
                            float bv = Bs64[tx + 16 * cc][kk];
                            acc[0][cc] = fmaf(a0, bv, acc[0][cc]);
                            acc[1][cc] = fmaf(a1, bv, acc[1][cc]);
                        }
                    }
                    __syncthreads();
                }
#pragma unroll
                for (int rep = 0; rep < 2; rep++)
#pragma unroll
                    for (int cc = 0; cc < 4; cc++)
                        gbuf[(ty * 2 + rep) * 2048 + jobx * 64 + tx + 16 * cc] = acc[rep][cc];
                __syncthreads();
            } else {
                // gates1 h-part: K=512 over h1in, B=Whh1 (zero at g==2)
                const int jobx = job - 64;
                const int j0 = jobx * 16;
                const float* brow = (gg < 2) ? Whh1 + (size_t)(gg * 512 + j0 + gjj) * 512
                                 : (gg == 3) ? Whh1 + (size_t)(1024 + j0 + gjj) * 512
                                 : (const float*)0;
                const float* arow = (mmq < 32) ? h1in + mmq * 512 : (const float*)0;
                float4 ra = arow ? *(const float4*)(arow + kq) : f4z;
                float4 rb = brow ? *(const float4*)(brow + kq) : f4z;
                float acc[2][4] = {{0,0,0,0},{0,0,0,0}};
                for (int kb = 0; kb < 32; kb++) {
                    if (mmq < 32) {
                        As32[mmq][kq + 0] = ra.x; As32[mmq][kq + 1] = ra.y;
                        As32[mmq][kq + 2] = ra.z; As32[mmq][kq + 3] = ra.w;
                    }
                    Bs64[mmq][kq + 0] = rb.x; Bs64[mmq][kq + 1] = rb.y;
                    Bs64[mmq][kq + 2] = rb.z; Bs64[mmq][kq + 3] = rb.w;
                    __syncthreads();
                    int kn = kb + 1;
                    if (kn < 32) {
                        int kl = kn * 16;
                        ra = arow ? *(const float4*)(arow + kl + kq) : f4z;
                        rb = brow ? *(const float4*)(brow + kl + kq) : f4z;
                    }
#pragma unroll
                    for (int kk = 0; kk < 16; kk++) {
                        float a0 = As32[ty * 2][kk], a1 = As32[ty * 2 + 1][kk];
#pragma unroll
                        for (int cc = 0; cc < 4; cc++) {
                            float bv = Bs64[tx + 16 * cc][kk];
                            acc[0][cc] = fmaf(a0, bv, acc[0][cc]);
                            acc[1][cc] = fmaf(a1, bv, acc[1][cc]);
                        }
                    }
                    __syncthreads();
                }
#pragma unroll
                for (int rep = 0; rep < 2; rep++)
#pragma unroll
                    for (int cc = 0; cc < 4; cc++)
                        gbuf1[(ty * 2 + rep) * 2048 + jobx * 64 + tx + 16 * cc] = acc[rep][cc];
                __syncthreads();
            }
        }
        grid_barrier();

        // ==== W2: gates0 finalize ctx-K pipelined (0..31) || logits-ctx pipelined (32..156)
        for (int job = bid; job < 157; job += NB) {
            if (job < 32) {
                const int j0 = job * 16;
                const float* brow = (gg < 2) ? Wih0 + (size_t)(gg * 512 + j0 + gjj) * 1536
                                 : (gg == 2) ? Wih0 + (size_t)(1024 + j0 + gjj) * 1536
                                 : (const float*)0;
                const float* arow = (mmq < 32) ? ctx + mmq * 1024 : (const float*)0;
                float acc[2][4];
#pragma unroll
                for (int rep = 0; rep < 2; rep++)
#pragma unroll
                    for (int cc = 0; cc < 4; cc++)
                        acc[rep][cc] = gbuf[(ty * 2 + rep) * 2048 + job * 64 + tx + 16 * cc];
                float4 ra = arow ? *(const float4*)(arow + kq) : f4z;
                float4 rb = brow ? *(const float4*)(brow + 512 + kq) : f4z;
                for (int kb = 0; kb < 64; kb++) {
                    if (mmq < 32) {
                        As32[mmq][kq + 0] = ra.x; As32[mmq][kq + 1] = ra.y;
                        As32[mmq][kq + 2] = ra.z; As32[mmq][kq + 3] = ra.w;
                    }
                    Bs64[mmq][kq + 0] = rb.x; Bs64[mmq][kq + 1] = rb.y;
                    Bs64[mmq][kq + 2] = rb.z; Bs64[mmq][kq + 3] = rb.w;
                    __syncthreads();
                    int kn = kb + 1;
                    if (kn < 64) {
                        int kl = kn * 16;
                        ra = arow ? *(const float4*)(arow + kl + kq) : f4z;
                        rb = brow ? *(const float4*)(brow + 512 + kl + kq) : f4z;
                    }
#pragma unroll
                    for (int kk = 0; kk < 16; kk++) {
                        float a0 = As32[ty * 2][kk], a1 = As32[ty * 2 + 1][kk];
#pragma unroll
                        for (int cc = 0; cc < 4; cc++) {
                            float bv = Bs64[tx + 16 * cc][kk];
                            acc[0][cc] = fmaf(a0, bv, acc[0][cc]);
                            acc[1][cc] = fmaf(a1, bv, acc[1][cc]);
                        }
                    }
                    __syncthreads();
                }
#pragma unroll
                for (int rep = 0; rep < 2; rep++)
#pragma unroll
                    for (int cc = 0; cc < 4; cc++)
                        sacc[ty * 2 + rep][tx + 16 * cc] = acc[rep][cc];
                __syncthreads();
                for (int i = tid; i < 512; i += 256) {
                    int b = i >> 4, jj = i & 15;
                    int j = j0 + jj;
                    float r_  = sacc[b][jj]      + bih0[j]        + bhh0[j];
                    float z_  = sacc[b][16 + jj] + bih0[512 + j]  + bhh0[512 + j];
                    float in_ = sacc[b][32 + jj] + bih0[1024 + j];
                    float hn_ = sacc[b][48 + jj] + bhh0[1024 + j];
                    float rr = 1.f / (1.f + expf(-r_));
                    float zz = 1.f / (1.f + expf(-z_));
                    float nn = tanhf(in_ + rr * hn_);
                    h0out[b * 512 + j] = (1.f - zz) * nn + zz * h0in[b * 512 + j];
                }
                __syncthreads();
            } else {
                // logits-ctx: pipelined float4, K in [512,1536)
                const int n0 = (job - 32) * 64;
                float4 ra, rb;
                rb = *(const float4*)(projW + (size_t)(n0 + mmq) * 1536 + 512 + kq);
                if (mmq < 32) ra = *(const float4*)(ctx + mmq * 1024 + kq);
                else ra = f4z;
                float acc[2][4] = {{0,0,0,0},{0,0,0,0}};
                for (int k0 = 512; k0 < 1536; k0 += 16) {
                    As16[kq + 0][mmq] = ra.x; As16[kq + 1][mmq] = ra.y;
                    As16[kq + 2][mmq] = ra.z; As16[kq + 3][mmq] = ra.w;
                    Bs16[kq + 0][mmq] = rb.x; Bs16[kq + 1][mmq] = rb.y;
                    Bs16[kq + 2][mmq] = rb.z; Bs16[kq + 3][mmq] = rb.w;
                    __syncthreads();
                    int kn = k0 + 16;
                    if (kn < 1536) {
                        rb = *(const float4*)(projW + (size_t)(n0 + mmq) * 1536 + kn + kq);
                        if (mmq < 32) ra = *(const float4*)(ctx + mmq * 1024 + (kn - 512) + kq);
                    }
#pragma unroll
                    for (int kk = 0; kk < 16; kk++) {
                        float a0 = As16[kk][ty], a1 = As16[kk][ty + 16];
#pragma unroll
                        for (int j = 0; j < 4; j++) {
                            float bv = Bs16[kk][tx + 16 * j];
                            acc[0][j] = fmaf(a0, bv, acc[0][j]);
                            acc[1][j] = fmaf(a1, bv, acc[1][j]);
                        }
                    }
                    __syncthreads();
                }
#pragma unroll
                for (int i = 0; i < 2; i++) {
                    int m = ty + 16 * i;
#pragma unroll
                    for (int j = 0; j < 4; j++) {
                        int n = n0 + tx + 16 * j;
                        logits[(size_t)m * VOCAB + n] = acc[i][j] + projb[n];
                    }
                }
                __syncthreads();
            }
        }
        grid_barrier();

        // ==== W3: gates1 finalize — x-part (K=512 over h0out), pipelined, 32 jobs
        for (int job = bid; job < 32; job += NB) {
            const int j0 = job * 16;
            const float* brow = (gg < 2) ? Wih1 + (size_t)(gg * 512 + j0 + gjj) * 512
                             : (gg == 2) ? Wih1 + (size_t)(1024 + j0 + gjj) * 512
                             : (const float*)0;
            const float* arow = (mmq < 32) ? h0out + mmq * 512 : (const float*)0;
            float acc[2][4];
#pragma unroll
            for (int rep = 0; rep < 2; rep++)
#pragma unroll
                for (int cc = 0; cc < 4; cc++)
                    acc[rep][cc] = gbuf1[(ty * 2 + rep) * 2048 + job * 64 + tx + 16 * cc];
            float4 ra = arow ? *(const float4*)(arow + kq) : f4z;
            float4 rb = brow ? *(const float4*)(brow + kq) : f4z;
            for (int kb = 0; kb < 32; kb++) {
                if (mmq < 32) {
                    As32[mmq][kq + 0] = ra.x; As32[mmq][kq + 1] = ra.y;
                    As32[mmq][kq + 2] = ra.z; As32[mmq][kq + 3] = ra.w;
                }
                Bs64[mmq][kq + 0] = rb.x; Bs64[mmq][kq + 1] = rb.y;
                Bs64[mmq][kq + 2] = rb.z; Bs64[mmq][kq + 3] = rb.w;
                __syncthreads();
                int kn = kb + 1;
                if (kn < 32) {
                    int kl = kn * 16;
                    ra = arow ? *(const float4*)(arow + kl + kq) : f4z;
                    rb = brow ? *(const float4*)(brow + kl + kq) : f4z;
                }
#pragma unroll
                for (int kk = 0; kk < 16; kk++) {
                    float a0 = As32[ty * 2][kk], a1 = As32[ty * 2 + 1][kk];
#pragma unroll
                    for (int cc = 0; cc < 4; cc++) {
                        float bv = Bs64[tx + 16 * cc][kk];
                        acc[0][cc] = fmaf(a0, bv, acc[0][cc]);
                        acc[1][cc] = fmaf(a1, bv, acc[1][cc]);
                    }
                }
                __syncthreads();
            }
#pragma unroll
            for (int rep = 0; rep < 2; rep++)
#pragma unroll
                for (int cc = 0; cc < 4; cc++)
                    sacc[ty * 2 + rep][tx + 16 * cc] = acc[rep][cc];
            __syncthreads();
            for (int i = tid; i < 512; i += 256) {
                int b = i >> 4, jj = i & 15;
                int j = j0 + jj;
                float r_  = sacc[b][jj]      + bih1[j]        + bhh1[j];
                float z_  = sacc[b][16 + jj] + bih1[512 + j]  + bhh1[512 + j];
                float in_ = sacc[b][32 + jj] + bih1[1024 + j];
                float hn_ = sacc[b][48 + jj] + bhh1[1024 + j];
                float rr = 1.f / (1.f + expf(-r_));
                float zz = 1.f / (1.f + expf(-z_));
                float nn = tanhf(in_ + rr * hn_);
                h1out[b * 512 + j] = (1.f - zz) * nn + zz * h1in[b * 512 + j];
            }
            __syncthreads();
        }
        grid_barrier();

        // ==== W4: logits += h1 part (K=512), pipelined float4, 125 jobs
        for (int job = bid; job < 125; job += NB) {
            const int n0 = job * 64;
            float4 ra, rb;
            rb = *(const float4*)(projW + (size_t)(n0 + mmq) * 1536 + kq);
            if (mmq < 32) ra = *(const float4*)(h1out + mmq * 512 + kq);
            else ra = f4z;
            float acc[2][4] = {{0,0,0,0},{0,0,0,0}};
            for (int k0 = 0; k0 < 512; k0 += 16) {
                As16[kq + 0][mmq] = ra.x; As16[kq + 1][mmq] = ra.y;
                As16[kq + 2][mmq] = ra.z; As16[kq + 3][mmq] = ra.w;
                Bs16[kq + 0][mmq] = rb.x; Bs16[kq + 1][mmq] = rb.y;
                Bs16[kq + 2][mmq] = rb.z; Bs16[kq + 3][mmq] = rb.w;
                __syncthreads();
                int kn = k0 + 16;
                if (kn < 512) {
                    rb = *(const float4*)(projW + (size_t)(n0 + mmq) * 1536 + kn + kq);
                    if (mmq < 32) ra = *(const float4*)(h1out + mmq * 512 + kn + kq);
                }
#pragma unroll
                for (int kk = 0; kk < 16; kk++) {
                    float a0 = As16[kk][ty], a1 = As16[kk][ty + 16];
#pragma unroll
                    for (int j = 0; j < 4; j++) {
                        float bv = Bs16[kk][tx + 16 * j];
                        acc[0][j] = fmaf(a0, bv, acc[0][j]);
                        acc[1][j] = fmaf(a1, bv, acc[1][j]);
                    }
                }
                __syncthreads();
            }
#pragma unroll
            for (int i = 0; i < 2; i++) {
                int m = ty + 16 * i;
#pragma unroll
                for (int j = 0; j < 4; j++) {
                    int n = n0 + tx + 16 * j;
                    logits[(size_t)m * VOCAB + n] += acc[i][j];
                }
            }
            __syncthreads();
        }
        grid_barrier();

        // ==== W5: argmax, 32 jobs
        for (int b = bid; b < 32; b += NB) {
            float best = -INFINITY; int bi = SENTINEL;
            for (int i = tid; i < VOCAB; i += 256) {
                float v = logits[(size_t)b * VOCAB + i];
                if (v > best) { best = v; bi = i; }
            }
            sv[tid] = best; si[tid] = bi; __syncthreads();
            for (int o = 128; o; o >>= 1) {
                if (tid < o) {
                    if (sv[tid + o] > sv[tid] ||
                        (sv[tid + o] == sv[tid] && si[tid + o] < si[tid])) {
                        sv[tid] = sv[tid + o]; si[tid] = si[tid + o];
                    }
                }
                __syncthreads();
            }
            if (tid == 0) { tok[b] = si[0]; out[b * MAXDEC + s + 1] = (float)si[0]; }
            __syncthreads();
        }
        grid_barrier();
    }
}

// ---------------- host ----------------
static inline unsigned cdiv(unsigned a, unsigned b) { return (a + b - 1) / b; }

static void gemm(const float* A, const float* Bm, const float* bias, float* C,
                 int M, int N, int K, int relu)
{
    dim3 grid(cdiv(M, 64), cdiv(N, 64));
    gemm_abt<<<grid, 256>>>(A, Bm, bias, C, M, N, K, relu);
}

enum {
    I_FEAT, I_CW1, I_CB1, I_CW2, I_CB2,
    I_EWIHF, I_EWHHF, I_EBIHF, I_EBHHF,
    I_EWIHB, I_EWHHB, I_EBIHB, I_EBHHB,
    I_BRW, I_BRB, I_EMB, I_AWE, I_AWD, I_AV,
    I_DWIH0, I_DWHH0, I_DBIH0, I_DBHH0,
    I_DWIH1, I_DWHH1, I_DBIH1, I_DBHH1,
    I_PW, I_PB, N_LOGICAL
};

extern "C" void kernel_launch(void* const* d_in, const int* in_sizes, int n_in,
                              void* d_out, int out_size)
{
    (void)out_size;
    static const int posA[N_LOGICAL] = {
        0, 1, 2, 3, 4,  5, 6, 7, 8,  9, 10, 11, 12,
        13, 14, 15, 16, 17, 18,  19, 20, 21, 22,  23, 24, 25, 26,  27, 28 };
    static const int posB[N_LOGICAL] = {
        26, 7, 5, 8, 6,  21, 19, 25, 23,  20, 18, 24, 22,
        3, 4, 17, 1, 0, 2,  11, 9, 15, 13,  12, 10, 16, 14,  27, 28 };
    static const long long esz[N_LOGICAL] = {
        4194304, 655360, 512, 1310720, 512,
        786432, 786432, 1536, 1536,  786432, 786432, 1536, 1536,
        1048576, 1024, 4096000, 524288, 262144, 512,
        2359296, 786432, 1536, 1536,  786432, 786432, 1536, 1536,
        12288000, 8000 };

    const int* pos = posA;
    if (n_in >= N_LOGICAL && in_sizes) {
        int misB = 0;
        for (int i = 0; i < N_LOGICAL; i++)
            if ((long long)in_sizes[posB[i]] != esz[i]) misB++;
        if (misB == 0) {
            int misA = 0;
            for (int i = 0; i < N_LOGICAL; i++)
                if ((long long)in_sizes[posA[i]] != esz[i]) misA++;
            if (misA > 0) pos = posB;
        }
    }

    const float* features = (const float*)d_in[pos[I_FEAT]];
    const float* conv_w1  = (const float*)d_in[pos[I_CW1]];
    const float* conv_b1  = (const float*)d_in[pos[I_CB1]];
    const float* conv_w2  = (const float*)d_in[pos[I_CW2]];
    const float* conv_b2  = (const float*)d_in[pos[I_CB2]];
    const float* Wih_f    = (const float*)d_in[pos[I_EWIHF]];
    const float* Whh_f    = (const float*)d_in[pos[I_EWHHF]];
    const float* bih_f    = (const float*)d_in[pos[I_EBIHF]];
    const float* bhh_f    = (const float*)d_in[pos[I_EBHHF]];
    const float* Wih_b    = (const float*)d_in[pos[I_EWIHB]];
    const float* Whh_b    = (const float*)d_in[pos[I_EWHHB]];
    const float* bih_b    = (const float*)d_in[pos[I_EBIHB]];
    const float* bhh_b    = (const float*)d_in[pos[I_EBHHB]];
    const float* bridge_W = (const float*)d_in[pos[I_BRW]];
    const float* bridge_b = (const float*)d_in[pos[I_BRB]];
    const float* emb      = (const float*)d_in[pos[I_EMB]];
    const float* attn_We  = (const float*)d_in[pos[I_AWE]];
    const float* attn_Wd  = (const float*)d_in[pos[I_AWD]];
    const float* attn_v   = (const float*)d_in[pos[I_AV]];
    const float* dWih0    = (const float*)d_in[pos[I_DWIH0]];
    const float* dWhh0    = (const float*)d_in[pos[I_DWHH0]];
    const float* dbih0    = (const float*)d_in[pos[I_DBIH0]];
    const float* dbhh0    = (const float*)d_in[pos[I_DBHH0]];
    const float* dWih1    = (const float*)d_in[pos[I_DWIH1]];
    const float* dWhh1    = (const float*)d_in[pos[I_DWHH1]];
    const float* dbih1    = (const float*)d_in[pos[I_DBIH1]];
    const float* dbhh1    = (const float*)d_in[pos[I_DBHH1]];
    const float* proj_W   = (const float*)d_in[pos[I_PW]];
    const float* proj_b   = (const float*)d_in[pos[I_PB]];
    float* out = (float*)d_out;

    float* S = nullptr;
    cudaGetSymbolAddress((void**)&S, g_scratch);

    float* patch   = S + OFF_PATCH;
    float* c1      = S + OFF_C1;
    float* c2      = S + OFF_C2;
    float* xtbc    = S + OFF_XTBC;
    float* gif     = S + OFF_GIF;
    float* gib     = S + OFF_GIB;
    float* encout  = S + OFF_ENCOUT;
    float* encproj = S + OFF_ENCPROJ;
    float* hbuf    = S + OFF_HBUF;
    float* comb    = S + OFF_COMB;

    int dev = 0; cudaGetDevice(&dev);
    int nsm = 0; cudaDeviceGetAttribute(&nsm, cudaDevAttrMultiProcessorCount, dev);
    if (nsm <= 0) nsm = 1;
    int occE = 0, occD = 0;
    cudaOccupancyMaxActiveBlocksPerMultiprocessor(&occE, encoder_loop_k, 256, 0);
    cudaOccupancyMaxActiveBlocksPerMultiprocessor(&occD, decoder_loop_k, 256, 0);
    if (occE < 1) occE = 1;
    if (occD < 1) occD = 1;
    long long ecap = (long long)nsm * occE;
    long long dcap = (long long)nsm * occD;
    int enc_blk = (int)(ecap < 32  ? ecap : 32);
    int dec_blk = (int)(dcap < 157 ? dcap : 157);

    im2col1<<<cdiv(8192u * 1280u, 256u), 256>>>(features, patch);
    gemm(patch, conv_w1, conv_b1, c1, 8192, 512, 1280, 1);
    im2col2<<<cdiv(4096u * 2560u, 256u), 256>>>(c1, patch);
    gemm(patch, conv_w2, conv_b2, c2, 4096, 512, 2560, 1);
    xpose_bt<<<cdiv(4096u * 512u, 256u), 256>>>(c2, xtbc);

    gemm(xtbc, Wih_f, bih_f, gif, 4096, 1536, 512, 0);
    gemm(xtbc, Wih_b, bih_b, gib, 4096, 1536, 512, 0);

    encoder_loop_k<<<enc_blk, 256>>>(gif, gib, Whh_f, Whh_b, bhh_f, bhh_b,
                                     encout, comb, hbuf);

    gemm(encout, attn_We, nullptr, encproj, 4096, 512, 1024, 0);

    decoder_loop_k<<<dec_blk, 256>>>(S, emb, attn_Wd, attn_v,
                                     dWih0, dWhh0, dbih0, dbhh0,
                                     dWih1, dWhh1, dbih1, dbhh1,
                                     proj_W, proj_b, bridge_W, bridge_b, out);
}